// round 5
// baseline (speedup 1.0000x reference)
#include <cuda_runtime.h>
#include <cuda_bf16.h>
#include <math.h>
#include <stdint.h>

// ---------------- Problem constants ----------------
#define NB     2
#define LQ     2048
#define DIM    320
#define NH     8
#define HD     40
#define BH     (NB * NH)         // 16
#define NROWS  (NB * LQ)         // 4096
#define FFD    1280
#define QKVN   960

typedef __nv_bfloat16 bf16;

// ---------------- Static scratch ----------------
__device__ bf16  g_lnb [NROWS * DIM];
__device__ bf16  g_qkv [NROWS * QKVN];
__device__ bf16  g_attn[NROWS * DIM];
__device__ float g_res [NROWS * DIM];
__device__ float g_res2[NROWS * DIM];
__device__ bf16  g_ffin[(size_t)NROWS * FFD];
__device__ bf16  g_wqkvt[QKVN * DIM];
__device__ bf16  g_wo1t [DIM * DIM];
__device__ bf16  g_w2t  [DIM * DIM];
__device__ bf16  g_wff1t[2 * FFD * DIM];   // interleaved: col 2j=x_j, 2j+1=gate_j
__device__ bf16  g_wff2t[DIM * FFD];
__device__ float g_bffi [2 * FFD];

// ---------------- Helpers ----------------
__device__ __forceinline__ uint32_t s2u(const void* p) {
    uint32_t a;
    asm("{ .reg .u64 t; cvta.to.shared.u64 t, %1; cvt.u32.u64 %0, t; }" : "=r"(a) : "l"(p));
    return a;
}
__device__ __forceinline__ void cpa16(uint32_t s, const void* g) {
    asm volatile("cp.async.cg.shared.global [%0], [%1], 16;\n" :: "r"(s), "l"(g));
}
__device__ __forceinline__ void cpa16z(uint32_t s, const void* g, int nb) {
    asm volatile("cp.async.cg.shared.global [%0], [%1], 16, %2;\n" :: "r"(s), "l"(g), "r"(nb));
}
__device__ __forceinline__ void cpa_commit() { asm volatile("cp.async.commit_group;\n" ::: "memory"); }
template<int N> __device__ __forceinline__ void cpa_wait() {
    asm volatile("cp.async.wait_group %0;\n" :: "n"(N) : "memory");
}
__device__ __forceinline__ void mma16816(float* d, const uint32_t* a, const uint32_t* b) {
    asm volatile("mma.sync.aligned.m16n8k16.row.col.f32.bf16.bf16.f32 "
        "{%0,%1,%2,%3}, {%4,%5,%6,%7}, {%8,%9}, {%0,%1,%2,%3};"
        : "+f"(d[0]), "+f"(d[1]), "+f"(d[2]), "+f"(d[3])
        : "r"(a[0]), "r"(a[1]), "r"(a[2]), "r"(a[3]), "r"(b[0]), "r"(b[1]));
}
__device__ __forceinline__ void ldm_x4t(uint32_t* r, uint32_t addr) {
    asm volatile("ldmatrix.sync.aligned.m8n8.x4.trans.shared.b16 {%0,%1,%2,%3}, [%4];"
        : "=r"(r[0]), "=r"(r[1]), "=r"(r[2]), "=r"(r[3]) : "r"(addr));
}
__device__ __forceinline__ void ldm_x2t(uint32_t* r, uint32_t addr) {
    asm volatile("ldmatrix.sync.aligned.m8n8.x2.trans.shared.b16 {%0,%1}, [%2];"
        : "=r"(r[0]), "=r"(r[1]) : "r"(addr));
}
__device__ __forceinline__ float fexp(float x) {
    float y = x * 1.44269504f;
    float z = y + 12582912.0f;
    int   ni = __float_as_int(z) - 0x4B400000;
    float f = y - (z - 12582912.0f);
    float p = 0.00961812910f;
    p = fmaf(p, f, 0.0555041087f);
    p = fmaf(p, f, 0.240226507f);
    p = fmaf(p, f, 0.693147182f);
    p = fmaf(p, f, 1.0f);
    return __int_as_float(__float_as_int(p) + (ni << 23));
}
__device__ __forceinline__ uint32_t packbf2(float a, float b) {
    __nv_bfloat162 h = __floats2bfloat162_rn(a, b);
    return *(uint32_t*)&h;
}

// ---------------- GEMM: C[M,N] = A[M,K] @ B[N,K]^T ----------------
#define ASTRIDE 40

struct GP {
    const bf16* A; int lda;
    const bf16* B; int ldb, nB;
    float* Cf; bf16* Cb; int ldc;
    const float* bias; const float* res;
    int M, N, K;
};

// EPI: 0 = fp32 out (+bias?)(+res?), 1 = bf16 out, 3 = fused GEGLU (interleaved)
template<int EPI>
__global__ void __launch_bounds__(256) gemm_k(GP p) {
    __shared__ bf16 sA[2][128 * ASTRIDE];
    __shared__ bf16 sB[2][128 * ASTRIDE];

    const int tid = threadIdx.x;
    const int wid = tid >> 5, lane = tid & 31;
    const int g = lane >> 2, t = lane & 3;
    const int wm = (wid >> 2) * 64, wn = (wid & 3) * 32;
    const int n0 = blockIdx.x * 128, m0 = blockIdx.y * 128;

    float acc[4][4][4];
    #pragma unroll
    for (int i = 0; i < 4; i++)
        #pragma unroll
        for (int j = 0; j < 4; j++)
            #pragma unroll
            for (int q = 0; q < 4; q++) acc[i][j][q] = 0.0f;

    auto load_stage = [&](int ch, int st) {
        const int k0 = ch * 32;
        #pragma unroll
        for (int j = 0; j < 2; j++) {
            int id = tid + j * 256;
            int r = id >> 2, c = id & 3;
            cpa16(s2u(&sA[st][r * ASTRIDE + c * 8]),
                  p.A + (size_t)(m0 + r) * p.lda + k0 + c * 8);
            int rn = n0 + r; if (rn >= p.nB) rn = p.nB - 1;
            cpa16(s2u(&sB[st][r * ASTRIDE + c * 8]),
                  p.B + (size_t)rn * p.ldb + k0 + c * 8);
        }
        cpa_commit();
    };

    auto compute_stage = [&](int st) {
        #pragma unroll
        for (int ks = 0; ks < 2; ks++) {
            const int kb = ks * 16 + 2 * t;
            uint32_t af[4][4], bfr[4][2];
            #pragma unroll
            for (int mt = 0; mt < 4; mt++) {
                const bf16* pa = &sA[st][(wm + mt * 16 + g) * ASTRIDE + kb];
                af[mt][0] = *(const uint32_t*)pa;
                af[mt][1] = *(const uint32_t*)(pa + 8 * ASTRIDE);
                af[mt][2] = *(const uint32_t*)(pa + 8);
                af[mt][3] = *(const uint32_t*)(pa + 8 * ASTRIDE + 8);
            }
            #pragma unroll
            for (int nt = 0; nt < 4; nt++) {
                const bf16* pb = &sB[st][(wn + nt * 8 + g) * ASTRIDE + kb];
                bfr[nt][0] = *(const uint32_t*)pb;
                bfr[nt][1] = *(const uint32_t*)(pb + 8);
            }
            #pragma unroll
            for (int mt = 0; mt < 4; mt++)
                #pragma unroll
                for (int nt = 0; nt < 4; nt++)
                    mma16816(acc[mt][nt], af[mt], bfr[nt]);
        }
    };

    const int NC = p.K >> 5;
    load_stage(0, 0);
    for (int i = 0; i < NC; i++) {
        if (i + 1 < NC) { load_stage(i + 1, (i + 1) & 1); cpa_wait<1>(); }
        else            { cpa_wait<0>(); }
        __syncthreads();
        compute_stage(i & 1);
        __syncthreads();
    }

    #pragma unroll
    for (int mt = 0; mt < 4; mt++) {
        const int r0 = m0 + wm + mt * 16 + g;
        const int r1 = r0 + 8;
        #pragma unroll
        for (int nt = 0; nt < 4; nt++) {
            const int cb = n0 + wn + nt * 8;
            if (cb >= p.N) continue;
            const int c = cb + 2 * t;
            float v0 = acc[mt][nt][0], v1 = acc[mt][nt][1];
            float v2 = acc[mt][nt][2], v3 = acc[mt][nt][3];
            if (EPI == 3) {
                v0 += p.bias[c]; v1 += p.bias[c + 1];
                v2 += p.bias[c]; v3 += p.bias[c + 1];
                float o0 = v0 * 0.5f * v1 * (1.0f + erff(v1 * 0.7071067811865476f));
                float o1 = v2 * 0.5f * v3 * (1.0f + erff(v3 * 0.7071067811865476f));
                int j = c >> 1;
                p.Cb[(size_t)r0 * p.ldc + j] = __float2bfloat16(o0);
                p.Cb[(size_t)r1 * p.ldc + j] = __float2bfloat16(o1);
            } else if (EPI == 1) {
                *(uint32_t*)(p.Cb + (size_t)r0 * p.ldc + c) = packbf2(v0, v1);
                *(uint32_t*)(p.Cb + (size_t)r1 * p.ldc + c) = packbf2(v2, v3);
            } else {
                if (p.bias) {
                    float2 bb = *(const float2*)(p.bias + c);
                    v0 += bb.x; v1 += bb.y; v2 += bb.x; v3 += bb.y;
                }
                if (p.res) {
                    float2 q0 = *(const float2*)(p.res + (size_t)r0 * p.ldc + c);
                    float2 q1 = *(const float2*)(p.res + (size_t)r1 * p.ldc + c);
                    v0 += q0.x; v1 += q0.y; v2 += q1.x; v3 += q1.y;
                }
                *(float2*)(p.Cf + (size_t)r0 * p.ldc + c) = make_float2(v0, v1);
                *(float2*)(p.Cf + (size_t)r1 * p.ldc + c) = make_float2(v2, v3);
            }
        }
    }
}

// ---------------- Fused flash attention ----------------
// grid (LQ/128, BH), 256 threads. Warp-tile: 16 q-rows x 128 k-cols.
// K tile: [128 seq][56 pad] (d cols 0..39 real, 40..47 zero)
// V tile: [128 seq][56 pad] natural layout; B-frags via ldmatrix.trans
#define KSTR 56
#define VSTR 56
#define FL_SMEM (2 * 128 * KSTR * 2 + 2 * 128 * VSTR * 2)   // 57344 B

__global__ void __launch_bounds__(256) flash_k(const bf16* __restrict__ qkv,
                                               bf16* __restrict__ attn) {
    extern __shared__ bf16 fsm[];
    bf16* sK = fsm;                      // [2][128*KSTR]
    bf16* sV = fsm + 2 * 128 * KSTR;     // [2][128*VSTR]

    const int tid = threadIdx.x, wid = tid >> 5, lane = tid & 31;
    const int g = lane >> 2, t = lane & 3;
    const int z = blockIdx.y, b = z >> 3, h = z & 7;
    const int m0 = blockIdx.x * 128;
    const float scale = 0.15811388300841897f;   // 1/sqrt(40)

    // Q fragments (d = 0..47; cols 40..47 zero)
    uint32_t qf[3][4];
    {
        const bf16* qb = qkv + (size_t)(b * LQ + m0 + wid * 16) * QKVN + h * HD;
        #pragma unroll
        for (int ks = 0; ks < 3; ks++) {
            int c0 = ks * 16 + 2 * t;
            qf[ks][0] = *(const uint32_t*)(qb + (size_t)g * QKVN + c0);
            qf[ks][1] = *(const uint32_t*)(qb + (size_t)(g + 8) * QKVN + c0);
            if (ks < 2) {
                qf[ks][2] = *(const uint32_t*)(qb + (size_t)g * QKVN + c0 + 8);
                qf[ks][3] = *(const uint32_t*)(qb + (size_t)(g + 8) * QKVN + c0 + 8);
            } else { qf[ks][2] = 0u; qf[ks][3] = 0u; }
        }
    }

    auto loadKV = [&](int kt, int st) {
        #pragma unroll
        for (int j = 0; j < 3; j++) {          // K: 128 rows x 6 chunks (5 real + zfill)
            int id = tid + j * 256;
            int r = id / 6, c = id % 6;
            uint32_t so = s2u(sK + st * 128 * KSTR + r * KSTR + c * 8);
            const bf16* gp = qkv + (size_t)(b * LQ + kt * 128 + r) * QKVN + DIM + h * HD + c * 8;
            cpa16z(so, gp, c < 5 ? 16 : 0);
        }
        #pragma unroll
        for (int j = 0; j < 3; j++) {          // V: 128 rows x 5 chunks (natural layout)
            int id = tid + j * 256;
            if (id < 640) {
                int r = id / 5, c = id % 5;
                uint32_t so = s2u(sV + st * 128 * VSTR + r * VSTR + c * 8);
                const bf16* gp = qkv + (size_t)(b * LQ + kt * 128 + r) * QKVN + 2 * DIM + h * HD + c * 8;
                cpa16(so, gp);
            }
        }
        cpa_commit();
    };

    float accO[5][4];
    #pragma unroll
    for (int i = 0; i < 5; i++)
        #pragma unroll
        for (int q = 0; q < 4; q++) accO[i][q] = 0.0f;
    float l0 = 0.0f, l1 = 0.0f;

    loadKV(0, 0);
    for (int kt = 0; kt < LQ / 128; kt++) {
        const int st = kt & 1;
        if (kt + 1 < LQ / 128) { loadKV(kt + 1, st ^ 1); cpa_wait<1>(); }
        else                   { cpa_wait<0>(); }
        __syncthreads();

        // ---- S = Q @ K^T ----
        float accS[16][4];
        #pragma unroll
        for (int i = 0; i < 16; i++)
            #pragma unroll
            for (int q = 0; q < 4; q++) accS[i][q] = 0.0f;

        const bf16* kb = sK + st * 128 * KSTR;
        #pragma unroll
        for (int ks = 0; ks < 3; ks++) {
            const int kc = ks * 16 + 2 * t;
            #pragma unroll
            for (int nt = 0; nt < 16; nt++) {
                const bf16* pb = kb + (nt * 8 + g) * KSTR + kc;
                uint32_t bfr[2] = { *(const uint32_t*)pb, *(const uint32_t*)(pb + 8) };
                mma16816(accS[nt], qf[ks], bfr);
            }
        }

        // ---- P = exp(S*scale) -> A-frags + rowsum ----
        uint32_t pf[8][4];
        #pragma unroll
        for (int ks2 = 0; ks2 < 8; ks2++) {
            float e0 = fexp(accS[2 * ks2][0] * scale), e1 = fexp(accS[2 * ks2][1] * scale);
            float e2 = fexp(accS[2 * ks2][2] * scale), e3 = fexp(accS[2 * ks2][3] * scale);
            float f0 = fexp(accS[2 * ks2 + 1][0] * scale), f1 = fexp(accS[2 * ks2 + 1][1] * scale);
            float f2 = fexp(accS[2 * ks2 + 1][2] * scale), f3 = fexp(accS[2 * ks2 + 1][3] * scale);
            l0 += (e0 + e1) + (f0 + f1);
            l1 += (e2 + e3) + (f2 + f3);
            pf[ks2][0] = packbf2(e0, e1);
            pf[ks2][1] = packbf2(e2, e3);
            pf[ks2][2] = packbf2(f0, f1);
            pf[ks2][3] = packbf2(f2, f3);
        }

        // ---- O += P @ V (B-frags via ldmatrix.trans on natural V) ----
        const bf16* vb = sV + st * 128 * VSTR;
        #pragma unroll
        for (int ks2 = 0; ks2 < 8; ks2++) {
            const int k0 = ks2 * 16;
            uint32_t bb[5][2];
            const int vrow = k0 + (lane & 7) + ((lane >> 3) & 1) * 8;
            #pragma unroll
            for (int pp = 0; pp < 2; pp++) {   // n-tiles {0,1} and {2,3}
                uint32_t addr = s2u(vb + vrow * VSTR + pp * 16 + (lane >> 4) * 8);
                uint32_t r4[4];
                ldm_x4t(r4, addr);
                bb[2 * pp][0] = r4[0]; bb[2 * pp][1] = r4[1];
                bb[2 * pp + 1][0] = r4[2]; bb[2 * pp + 1][1] = r4[3];
            }
            {                                   // n-tile 4 (d 32..39)
                uint32_t addr = s2u(vb + vrow * VSTR + 32);
                ldm_x2t(bb[4], addr);
            }
            #pragma unroll
            for (int nt = 0; nt < 5; nt++)
                mma16816(accO[nt], pf[ks2], bb[nt]);
        }
        __syncthreads();
    }

    // ---- normalize + write ----
    l0 += __shfl_xor_sync(0xffffffffu, l0, 1);
    l0 += __shfl_xor_sync(0xffffffffu, l0, 2);
    l1 += __shfl_xor_sync(0xffffffffu, l1, 1);
    l1 += __shfl_xor_sync(0xffffffffu, l1, 2);
    const float i0 = 1.0f / l0, i1 = 1.0f / l1;
    const int r0 = b * LQ + m0 + wid * 16 + g, r1 = r0 + 8;
    #pragma unroll
    for (int nt = 0; nt < 5; nt++) {
        int col = h * HD + nt * 8 + 2 * t;
        *(uint32_t*)(attn + (size_t)r0 * DIM + col) = packbf2(accO[nt][0] * i0, accO[nt][1] * i0);
        *(uint32_t*)(attn + (size_t)r1 * DIM + col) = packbf2(accO[nt][2] * i1, accO[nt][3] * i1);
    }
}

// ---------------- LayerNorm (fp32 in -> bf16 out) ----------------
__global__ void ln_k(const float* __restrict__ x, const float* __restrict__ g,
                     const float* __restrict__ b, bf16* __restrict__ y) {
    __shared__ float red[32];
    int row = blockIdx.x, tid = threadIdx.x;
    float v = x[row * DIM + tid];
    float s = v;
    #pragma unroll
    for (int o = 16; o > 0; o >>= 1) s += __shfl_xor_sync(0xffffffffu, s, o);
    if ((tid & 31) == 0) red[tid >> 5] = s;
    __syncthreads();
    if (tid < 32) {
        float t2 = (tid < (DIM / 32)) ? red[tid] : 0.0f;
        #pragma unroll
        for (int o = 16; o > 0; o >>= 1) t2 += __shfl_xor_sync(0xffffffffu, t2, o);
        if (tid == 0) red[0] = t2;
    }
    __syncthreads();
    float mean = red[0] * (1.0f / DIM);
    __syncthreads();
    float d = v - mean;
    float s2 = d * d;
    #pragma unroll
    for (int o = 16; o > 0; o >>= 1) s2 += __shfl_xor_sync(0xffffffffu, s2, o);
    if ((tid & 31) == 0) red[tid >> 5] = s2;
    __syncthreads();
    if (tid < 32) {
        float t2 = (tid < (DIM / 32)) ? red[tid] : 0.0f;
        #pragma unroll
        for (int o = 16; o > 0; o >>= 1) t2 += __shfl_xor_sync(0xffffffffu, t2, o);
        if (tid == 0) red[0] = t2;
    }
    __syncthreads();
    float var = red[0] * (1.0f / DIM);
    y[row * DIM + tid] = __float2bfloat16(d * rsqrtf(var + 1e-5f) * g[tid] + b[tid]);
}

// ---------------- Merged prep ----------------
__global__ void prep_k(const float* __restrict__ wq1, const float* __restrict__ wk1,
                       const float* __restrict__ wv1, const float* __restrict__ wo1,
                       const float* __restrict__ wvh, const float* __restrict__ wo2,
                       const float* __restrict__ wff1, const float* __restrict__ wff2,
                       const float* __restrict__ bff1) {
    int idx = blockIdx.x * 256 + threadIdx.x;
    if (idx < 102400) {
        int n = idx % 320, k = idx / 320;
        float s = 0.0f;
        for (int j = 0; j < 320; j++) s += wvh[k * 320 + j] * wo2[j * 320 + n];
        g_w2t[n * 320 + k] = __float2bfloat16(s);
    } else if (idx < 204800) {
        int i = idx - 102400; int n = i / 320, k = i % 320;
        g_wqkvt[i] = __float2bfloat16(wq1[k * 320 + n]);
    } else if (idx < 307200) {
        int i = idx - 204800; int n = i / 320, k = i % 320;
        g_wqkvt[102400 + i] = __float2bfloat16(wk1[k * 320 + n]);
    } else if (idx < 409600) {
        int i = idx - 307200; int n = i / 320, k = i % 320;
        g_wqkvt[204800 + i] = __float2bfloat16(wv1[k * 320 + n]);
    } else if (idx < 512000) {
        int i = idx - 409600; int n = i / 320, k = i % 320;
        g_wo1t[i] = __float2bfloat16(wo1[k * 320 + n]);
    } else if (idx < 921600) {
        int i = idx - 512000; int n = i / 1280, k = i % 1280;
        g_wff2t[i] = __float2bfloat16(wff2[k * 320 + n]);
    } else if (idx < 1740800) {
        int i = idx - 921600; int c = i / 320, k = i % 320;
        int j = (c >> 1) + (c & 1) * FFD;
        g_wff1t[i] = __float2bfloat16(wff1[(size_t)k * 2 * FFD + j]);
    } else if (idx < 1743360) {
        int c = idx - 1740800;
        g_bffi[c] = bff1[(c >> 1) + (c & 1) * FFD];
    }
}

// ---------------- Launch ----------------
extern "C" void kernel_launch(void* const* d_in, const int* in_sizes, int n_in,
                              void* d_out, int out_size) {
    (void)in_sizes; (void)n_in; (void)out_size;
    const float* hidden = (const float*)d_in[0];
    const float* ln1_g = (const float*)d_in[2];
    const float* ln1_b = (const float*)d_in[3];
    const float* wq1   = (const float*)d_in[4];
    const float* wk1   = (const float*)d_in[5];
    const float* wv1   = (const float*)d_in[6];
    const float* wo1   = (const float*)d_in[7];
    const float* bo1   = (const float*)d_in[8];
    const float* ln2_g = (const float*)d_in[9];
    const float* ln2_b = (const float*)d_in[10];
    const float* wvh   = (const float*)d_in[13];
    const float* wo2   = (const float*)d_in[14];
    const float* bo2   = (const float*)d_in[15];
    const float* ln3_g = (const float*)d_in[16];
    const float* ln3_b = (const float*)d_in[17];
    const float* wff1  = (const float*)d_in[18];
    const float* bff1  = (const float*)d_in[19];
    const float* wff2  = (const float*)d_in[20];
    const float* bff2  = (const float*)d_in[21];
    float* out = (float*)d_out;

    bf16 *s_lnb, *s_qkv, *s_attn, *s_ffin;
    bf16 *s_wqkvt, *s_wo1t, *s_w2t, *s_wff1t, *s_wff2t;
    float *s_res, *s_res2, *s_bffi;
    cudaGetSymbolAddress((void**)&s_lnb, g_lnb);
    cudaGetSymbolAddress((void**)&s_qkv, g_qkv);
    cudaGetSymbolAddress((void**)&s_attn, g_attn);
    cudaGetSymbolAddress((void**)&s_res, g_res);
    cudaGetSymbolAddress((void**)&s_res2, g_res2);
    cudaGetSymbolAddress((void**)&s_ffin, g_ffin);
    cudaGetSymbolAddress((void**)&s_wqkvt, g_wqkvt);
    cudaGetSymbolAddress((void**)&s_wo1t, g_wo1t);
    cudaGetSymbolAddress((void**)&s_w2t, g_w2t);
    cudaGetSymbolAddress((void**)&s_wff1t, g_wff1t);
    cudaGetSymbolAddress((void**)&s_wff2t, g_wff2t);
    cudaGetSymbolAddress((void**)&s_bffi, g_bffi);

    cudaFuncSetAttribute(flash_k, cudaFuncAttributeMaxDynamicSharedMemorySize, FL_SMEM);

    GP p{};

    // 1. weight prep
    prep_k<<<(1743360 + 255) / 256, 256>>>(wq1, wk1, wv1, wo1, wvh, wo2, wff1, wff2, bff1);

    // 2. LN1 + fused QKV GEMM
    ln_k<<<NROWS, DIM>>>(hidden, ln1_g, ln1_b, s_lnb);
    p = GP{ s_lnb, DIM,  s_wqkvt, DIM, QKVN,
            nullptr, s_qkv, QKVN,  nullptr, nullptr, NROWS, QKVN, DIM };
    gemm_k<1><<<dim3(8, 32), 256>>>(p);

    // 3. fused flash attention (V transposed on the fly via ldmatrix.trans)
    flash_k<<<dim3(LQ / 128, BH), 256, FL_SMEM>>>(s_qkv, s_attn);

    // 4. wo1 + bias + residual
    p = GP{ s_attn, DIM,  s_wo1t, DIM, DIM,
            s_res, nullptr, DIM,  bo1, hidden, NROWS, DIM, DIM };
    gemm_k<0><<<dim3(3, 32), 256>>>(p);

    // 5. LN2 + folded cross-attn + residual
    ln_k<<<NROWS, DIM>>>(s_res, ln2_g, ln2_b, s_lnb);
    p = GP{ s_lnb, DIM,  s_w2t, DIM, DIM,
            s_res2, nullptr, DIM,  bo2, s_res, NROWS, DIM, DIM };
    gemm_k<0><<<dim3(3, 32), 256>>>(p);

    // 6. LN3 + FF1 (fused GEGLU) + FF2 + residual
    ln_k<<<NROWS, DIM>>>(s_res2, ln3_g, ln3_b, s_lnb);
    p = GP{ s_lnb, DIM,  s_wff1t, DIM, 2 * FFD,
            nullptr, s_ffin, FFD,  s_bffi, nullptr, NROWS, 2 * FFD, DIM };
    gemm_k<3><<<dim3(20, 32), 256>>>(p);
    p = GP{ s_ffin, FFD,  s_wff2t, FFD, DIM,
            out, nullptr, DIM,  bff2, s_res2, NROWS, DIM, FFD };
    gemm_k<0><<<dim3(3, 32), 256>>>(p);
}

// round 6
// speedup vs baseline: 1.0932x; 1.0932x over previous
#include <cuda_runtime.h>
#include <cuda_bf16.h>
#include <math.h>
#include <stdint.h>

// ---------------- Problem constants ----------------
#define NB     2
#define LQ     2048
#define DIM    320
#define NH     8
#define HD     40
#define BH     (NB * NH)         // 16
#define NROWS  (NB * LQ)         // 4096
#define FFD    1280
#define QKVN   960

typedef __nv_bfloat16 bf16;

// ---------------- Static scratch ----------------
__device__ bf16  g_lnb [NROWS * DIM];
__device__ bf16  g_qkv [NROWS * QKVN];
__device__ bf16  g_attn[NROWS * DIM];
__device__ float g_res [NROWS * DIM];
__device__ float g_res2[NROWS * DIM];
__device__ bf16  g_ffin[(size_t)NROWS * FFD];
__device__ bf16  g_wqkvt[QKVN * DIM];
__device__ bf16  g_wo1t [DIM * DIM];
__device__ bf16  g_w2t  [DIM * DIM];
__device__ bf16  g_wff1t[2 * FFD * DIM];   // interleaved: col 2j=x_j, 2j+1=gate_j
__device__ bf16  g_wff2t[DIM * FFD];
__device__ float g_bffi [2 * FFD];

// ---------------- Helpers ----------------
__device__ __forceinline__ uint32_t s2u(const void* p) {
    uint32_t a;
    asm("{ .reg .u64 t; cvta.to.shared.u64 t, %1; cvt.u32.u64 %0, t; }" : "=r"(a) : "l"(p));
    return a;
}
__device__ __forceinline__ void cpa16(uint32_t s, const void* g) {
    asm volatile("cp.async.cg.shared.global [%0], [%1], 16;\n" :: "r"(s), "l"(g));
}
__device__ __forceinline__ void cpa16z(uint32_t s, const void* g, int nb) {
    asm volatile("cp.async.cg.shared.global [%0], [%1], 16, %2;\n" :: "r"(s), "l"(g), "r"(nb));
}
__device__ __forceinline__ void cpa_commit() { asm volatile("cp.async.commit_group;\n" ::: "memory"); }
template<int N> __device__ __forceinline__ void cpa_wait() {
    asm volatile("cp.async.wait_group %0;\n" :: "n"(N) : "memory");
}
__device__ __forceinline__ void mma16816(float* d, const uint32_t* a, const uint32_t* b) {
    asm volatile("mma.sync.aligned.m16n8k16.row.col.f32.bf16.bf16.f32 "
        "{%0,%1,%2,%3}, {%4,%5,%6,%7}, {%8,%9}, {%0,%1,%2,%3};"
        : "+f"(d[0]), "+f"(d[1]), "+f"(d[2]), "+f"(d[3])
        : "r"(a[0]), "r"(a[1]), "r"(a[2]), "r"(a[3]), "r"(b[0]), "r"(b[1]));
}
__device__ __forceinline__ void ldm_x4(uint32_t* r, uint32_t addr) {
    asm volatile("ldmatrix.sync.aligned.m8n8.x4.shared.b16 {%0,%1,%2,%3}, [%4];"
        : "=r"(r[0]), "=r"(r[1]), "=r"(r[2]), "=r"(r[3]) : "r"(addr));
}
__device__ __forceinline__ void ldm_x4t(uint32_t* r, uint32_t addr) {
    asm volatile("ldmatrix.sync.aligned.m8n8.x4.trans.shared.b16 {%0,%1,%2,%3}, [%4];"
        : "=r"(r[0]), "=r"(r[1]), "=r"(r[2]), "=r"(r[3]) : "r"(addr));
}
__device__ __forceinline__ void ldm_x2t(uint32_t* r, uint32_t addr) {
    asm volatile("ldmatrix.sync.aligned.m8n8.x2.trans.shared.b16 {%0,%1}, [%2];"
        : "=r"(r[0]), "=r"(r[1]) : "r"(addr));
}
__device__ __forceinline__ float fexp(float x) {
    float y = x * 1.44269504f;
    float z = y + 12582912.0f;
    int   ni = __float_as_int(z) - 0x4B400000;
    float f = y - (z - 12582912.0f);
    float p = 0.00961812910f;
    p = fmaf(p, f, 0.0555041087f);
    p = fmaf(p, f, 0.240226507f);
    p = fmaf(p, f, 0.693147182f);
    p = fmaf(p, f, 1.0f);
    return __int_as_float(__float_as_int(p) + (ni << 23));
}
__device__ __forceinline__ uint32_t packbf2(float a, float b) {
    __nv_bfloat162 h = __floats2bfloat162_rn(a, b);
    return *(uint32_t*)&h;
}

// ---------------- GEMM: C[M,N] = A[M,K] @ B[N,K]^T ----------------
#define ASTRIDE 40

struct GP {
    const bf16* A; int lda;
    const bf16* B; int ldb, nB;
    float* Cf; bf16* Cb; int ldc;
    const float* bias; const float* res;
    int M, N, K;
};

// EPI: 0 = fp32 out (+bias?)(+res?), 1 = bf16 out, 3 = fused GEGLU (interleaved)
// BN: 128 (8 warps of 64x32) or 64 (8 warps of 32x32)
template<int EPI, int BN>
__global__ void __launch_bounds__(256, 2) gemm_k(GP p) {
    constexpr int MT = (BN == 128) ? 4 : 2;
    __shared__ bf16 sA[2][128 * ASTRIDE];
    __shared__ bf16 sB[2][BN * ASTRIDE];

    const int tid = threadIdx.x;
    const int wid = tid >> 5, lane = tid & 31;
    const int g = lane >> 2, t = lane & 3;
    const int wm = (BN == 128) ? (wid >> 2) * 64 : (wid >> 1) * 32;
    const int wn = (BN == 128) ? (wid & 3) * 32 : (wid & 1) * 32;
    const int n0 = blockIdx.x * BN, m0 = blockIdx.y * 128;

    float acc[MT][4][4];
    #pragma unroll
    for (int i = 0; i < MT; i++)
        #pragma unroll
        for (int j = 0; j < 4; j++)
            #pragma unroll
            for (int q = 0; q < 4; q++) acc[i][j][q] = 0.0f;

    auto load_stage = [&](int ch, int st) {
        const int k0 = ch * 32;
        #pragma unroll
        for (int j = 0; j < 2; j++) {
            int id = tid + j * 256;
            int r = id >> 2, c = id & 3;
            cpa16(s2u(&sA[st][r * ASTRIDE + c * 8]),
                  p.A + (size_t)(m0 + r) * p.lda + k0 + c * 8);
        }
        #pragma unroll
        for (int j = 0; j < BN / 64; j++) {
            int id = tid + j * 256;
            int r = id >> 2, c = id & 3;
            int rn = n0 + r; if (rn >= p.nB) rn = p.nB - 1;
            cpa16(s2u(&sB[st][r * ASTRIDE + c * 8]),
                  p.B + (size_t)rn * p.ldb + k0 + c * 8);
        }
        cpa_commit();
    };

    auto compute_stage = [&](int st) {
        #pragma unroll
        for (int ks = 0; ks < 2; ks++) {
            const int kb = ks * 16 + 2 * t;
            uint32_t af[MT][4], bfr[4][2];
            #pragma unroll
            for (int mt = 0; mt < MT; mt++) {
                const bf16* pa = &sA[st][(wm + mt * 16 + g) * ASTRIDE + kb];
                af[mt][0] = *(const uint32_t*)pa;
                af[mt][1] = *(const uint32_t*)(pa + 8 * ASTRIDE);
                af[mt][2] = *(const uint32_t*)(pa + 8);
                af[mt][3] = *(const uint32_t*)(pa + 8 * ASTRIDE + 8);
            }
            #pragma unroll
            for (int nt = 0; nt < 4; nt++) {
                const bf16* pb = &sB[st][(wn + nt * 8 + g) * ASTRIDE + kb];
                bfr[nt][0] = *(const uint32_t*)pb;
                bfr[nt][1] = *(const uint32_t*)(pb + 8);
            }
            #pragma unroll
            for (int mt = 0; mt < MT; mt++)
                #pragma unroll
                for (int nt = 0; nt < 4; nt++)
                    mma16816(acc[mt][nt], af[mt], bfr[nt]);
        }
    };

    const int NC = p.K >> 5;
    load_stage(0, 0);
    for (int i = 0; i < NC; i++) {
        if (i + 1 < NC) { load_stage(i + 1, (i + 1) & 1); cpa_wait<1>(); }
        else            { cpa_wait<0>(); }
        __syncthreads();
        compute_stage(i & 1);
        __syncthreads();
    }

    #pragma unroll
    for (int mt = 0; mt < MT; mt++) {
        const int r0 = m0 + wm + mt * 16 + g;
        const int r1 = r0 + 8;
        #pragma unroll
        for (int nt = 0; nt < 4; nt++) {
            const int cb = n0 + wn + nt * 8;
            if (cb >= p.N) continue;
            const int c = cb + 2 * t;
            float v0 = acc[mt][nt][0], v1 = acc[mt][nt][1];
            float v2 = acc[mt][nt][2], v3 = acc[mt][nt][3];
            if (EPI == 3) {
                v0 += p.bias[c]; v1 += p.bias[c + 1];
                v2 += p.bias[c]; v3 += p.bias[c + 1];
                float o0 = v0 * 0.5f * v1 * (1.0f + erff(v1 * 0.7071067811865476f));
                float o1 = v2 * 0.5f * v3 * (1.0f + erff(v3 * 0.7071067811865476f));
                int j = c >> 1;
                p.Cb[(size_t)r0 * p.ldc + j] = __float2bfloat16(o0);
                p.Cb[(size_t)r1 * p.ldc + j] = __float2bfloat16(o1);
            } else if (EPI == 1) {
                *(uint32_t*)(p.Cb + (size_t)r0 * p.ldc + c) = packbf2(v0, v1);
                *(uint32_t*)(p.Cb + (size_t)r1 * p.ldc + c) = packbf2(v2, v3);
            } else {
                if (p.bias) {
                    float2 bb = *(const float2*)(p.bias + c);
                    v0 += bb.x; v1 += bb.y; v2 += bb.x; v3 += bb.y;
                }
                if (p.res) {
                    float2 q0 = *(const float2*)(p.res + (size_t)r0 * p.ldc + c);
                    float2 q1 = *(const float2*)(p.res + (size_t)r1 * p.ldc + c);
                    v0 += q0.x; v1 += q0.y; v2 += q1.x; v3 += q1.y;
                }
                *(float2*)(p.Cf + (size_t)r0 * p.ldc + c) = make_float2(v0, v1);
                *(float2*)(p.Cf + (size_t)r1 * p.ldc + c) = make_float2(v2, v3);
            }
        }
    }
}

// ---------------- Fused flash attention (v2: half-split, 2 CTAs/SM) ----------
#define KSTR 56
#define VSTR 56
#define FL_SMEM (2 * 128 * KSTR * 2 + 2 * 128 * VSTR * 2)   // 57344 B

__global__ void __launch_bounds__(256, 2) flash_k(const bf16* __restrict__ qkv,
                                                  bf16* __restrict__ attn) {
    extern __shared__ bf16 fsm[];
    bf16* sK = fsm;                      // [2][128*KSTR]
    bf16* sV = fsm + 2 * 128 * KSTR;     // [2][128*VSTR]

    const int tid = threadIdx.x, wid = tid >> 5, lane = tid & 31;
    const int g = lane >> 2, t = lane & 3;
    const int z = blockIdx.y, b = z >> 3, h = z & 7;
    const int m0 = blockIdx.x * 128;
    const float scale = 0.15811388300841897f;   // 1/sqrt(40)

    // ldmatrix lane-mapping constants
    const int lrow = (lane & 7) + ((lane >> 4) << 3);     // K (non-trans x4)
    const int lcol = ((lane >> 3) & 1) << 3;
    const int vlrow = (lane & 7) + (((lane >> 3) & 1) << 3);  // V (trans)

    // Q fragments (d = 0..47; cols 40..47 zero)
    uint32_t qf[3][4];
    {
        const bf16* qb = qkv + (size_t)(b * LQ + m0 + wid * 16) * QKVN + h * HD;
        #pragma unroll
        for (int ks = 0; ks < 3; ks++) {
            int c0 = ks * 16 + 2 * t;
            qf[ks][0] = *(const uint32_t*)(qb + (size_t)g * QKVN + c0);
            qf[ks][1] = *(const uint32_t*)(qb + (size_t)(g + 8) * QKVN + c0);
            if (ks < 2) {
                qf[ks][2] = *(const uint32_t*)(qb + (size_t)g * QKVN + c0 + 8);
                qf[ks][3] = *(const uint32_t*)(qb + (size_t)(g + 8) * QKVN + c0 + 8);
            } else { qf[ks][2] = 0u; qf[ks][3] = 0u; }
        }
    }

    auto loadKV = [&](int kt, int st) {
        #pragma unroll
        for (int j = 0; j < 3; j++) {          // K: 128 rows x 6 chunks (5 real + zfill)
            int id = tid + j * 256;
            int r = id / 6, c = id % 6;
            uint32_t so = s2u(sK + st * 128 * KSTR + r * KSTR + c * 8);
            const bf16* gp = qkv + (size_t)(b * LQ + kt * 128 + r) * QKVN + DIM + h * HD + c * 8;
            cpa16z(so, gp, c < 5 ? 16 : 0);
        }
        #pragma unroll
        for (int j = 0; j < 3; j++) {          // V: 128 rows x 5 chunks (natural layout)
            int id = tid + j * 256;
            if (id < 640) {
                int r = id / 5, c = id % 5;
                uint32_t so = s2u(sV + st * 128 * VSTR + r * VSTR + c * 8);
                const bf16* gp = qkv + (size_t)(b * LQ + kt * 128 + r) * QKVN + 2 * DIM + h * HD + c * 8;
                cpa16(so, gp);
            }
        }
        cpa_commit();
    };

    float accO[5][4];
    #pragma unroll
    for (int i = 0; i < 5; i++)
        #pragma unroll
        for (int q = 0; q < 4; q++) accO[i][q] = 0.0f;
    float l0 = 0.0f, l1 = 0.0f;

    loadKV(0, 0);
    for (int kt = 0; kt < LQ / 128; kt++) {
        const int st = kt & 1;
        if (kt + 1 < LQ / 128) { loadKV(kt + 1, st ^ 1); cpa_wait<1>(); }
        else                   { cpa_wait<0>(); }
        __syncthreads();

        const bf16* kb = sK + st * 128 * KSTR;
        const bf16* vb = sV + st * 128 * VSTR;

        #pragma unroll
        for (int half = 0; half < 2; half++) {
            // ---- S half = Q @ K^T (64 cols) ----
            float accS[8][4];
            #pragma unroll
            for (int i = 0; i < 8; i++)
                #pragma unroll
                for (int q = 0; q < 4; q++) accS[i][q] = 0.0f;

            #pragma unroll
            for (int ks = 0; ks < 3; ks++) {
                #pragma unroll
                for (int pair = 0; pair < 4; pair++) {
                    uint32_t r4[4];
                    uint32_t addr = s2u(kb + (half * 64 + pair * 16 + lrow) * KSTR
                                           + ks * 16 + lcol);
                    ldm_x4(r4, addr);
                    mma16816(accS[2 * pair], qf[ks], r4);
                    mma16816(accS[2 * pair + 1], qf[ks], r4 + 2);
                }
            }

            // ---- P = exp(S*scale) -> A-frags + rowsum ----
            uint32_t pf[4][4];
            #pragma unroll
            for (int ks2 = 0; ks2 < 4; ks2++) {
                float e0 = fexp(accS[2 * ks2][0] * scale), e1 = fexp(accS[2 * ks2][1] * scale);
                float e2 = fexp(accS[2 * ks2][2] * scale), e3 = fexp(accS[2 * ks2][3] * scale);
                float f0 = fexp(accS[2 * ks2 + 1][0] * scale), f1 = fexp(accS[2 * ks2 + 1][1] * scale);
                float f2 = fexp(accS[2 * ks2 + 1][2] * scale), f3 = fexp(accS[2 * ks2 + 1][3] * scale);
                l0 += (e0 + e1) + (f0 + f1);
                l1 += (e2 + e3) + (f2 + f3);
                pf[ks2][0] = packbf2(e0, e1);
                pf[ks2][1] = packbf2(e2, e3);
                pf[ks2][2] = packbf2(f0, f1);
                pf[ks2][3] = packbf2(f2, f3);
            }

            // ---- O += P @ V (B-frags via ldmatrix.trans on natural V) ----
            #pragma unroll
            for (int ks2 = 0; ks2 < 4; ks2++) {
                const int vrow = half * 64 + ks2 * 16 + vlrow;
                uint32_t bb[5][2];
                #pragma unroll
                for (int pp = 0; pp < 2; pp++) {
                    uint32_t addr = s2u(vb + vrow * VSTR + pp * 16 + (lane >> 4) * 8);
                    uint32_t r4[4];
                    ldm_x4t(r4, addr);
                    bb[2 * pp][0] = r4[0]; bb[2 * pp][1] = r4[1];
                    bb[2 * pp + 1][0] = r4[2]; bb[2 * pp + 1][1] = r4[3];
                }
                {
                    uint32_t addr = s2u(vb + vrow * VSTR + 32);
                    ldm_x2t(bb[4], addr);
                }
                #pragma unroll
                for (int nt = 0; nt < 5; nt++)
                    mma16816(accO[nt], pf[ks2], bb[nt]);
            }
        }
        __syncthreads();
    }

    // ---- normalize + write ----
    l0 += __shfl_xor_sync(0xffffffffu, l0, 1);
    l0 += __shfl_xor_sync(0xffffffffu, l0, 2);
    l1 += __shfl_xor_sync(0xffffffffu, l1, 1);
    l1 += __shfl_xor_sync(0xffffffffu, l1, 2);
    const float i0 = 1.0f / l0, i1 = 1.0f / l1;
    const int r0 = b * LQ + m0 + wid * 16 + g, r1 = r0 + 8;
    #pragma unroll
    for (int nt = 0; nt < 5; nt++) {
        int col = h * HD + nt * 8 + 2 * t;
        *(uint32_t*)(attn + (size_t)r0 * DIM + col) = packbf2(accO[nt][0] * i0, accO[nt][1] * i0);
        *(uint32_t*)(attn + (size_t)r1 * DIM + col) = packbf2(accO[nt][2] * i1, accO[nt][3] * i1);
    }
}

// ---------------- LayerNorm (fp32 in -> bf16 out) ----------------
__global__ void ln_k(const float* __restrict__ x, const float* __restrict__ g,
                     const float* __restrict__ b, bf16* __restrict__ y) {
    __shared__ float red[32];
    int row = blockIdx.x, tid = threadIdx.x;
    float v = x[row * DIM + tid];
    float s = v;
    #pragma unroll
    for (int o = 16; o > 0; o >>= 1) s += __shfl_xor_sync(0xffffffffu, s, o);
    if ((tid & 31) == 0) red[tid >> 5] = s;
    __syncthreads();
    if (tid < 32) {
        float t2 = (tid < (DIM / 32)) ? red[tid] : 0.0f;
        #pragma unroll
        for (int o = 16; o > 0; o >>= 1) t2 += __shfl_xor_sync(0xffffffffu, t2, o);
        if (tid == 0) red[0] = t2;
    }
    __syncthreads();
    float mean = red[0] * (1.0f / DIM);
    __syncthreads();
    float d = v - mean;
    float s2 = d * d;
    #pragma unroll
    for (int o = 16; o > 0; o >>= 1) s2 += __shfl_xor_sync(0xffffffffu, s2, o);
    if ((tid & 31) == 0) red[tid >> 5] = s2;
    __syncthreads();
    if (tid < 32) {
        float t2 = (tid < (DIM / 32)) ? red[tid] : 0.0f;
        #pragma unroll
        for (int o = 16; o > 0; o >>= 1) t2 += __shfl_xor_sync(0xffffffffu, t2, o);
        if (tid == 0) red[0] = t2;
    }
    __syncthreads();
    float var = red[0] * (1.0f / DIM);
    y[row * DIM + tid] = __float2bfloat16(d * rsqrtf(var + 1e-5f) * g[tid] + b[tid]);
}

// ---------------- Merged prep ----------------
__global__ void prep_k(const float* __restrict__ wq1, const float* __restrict__ wk1,
                       const float* __restrict__ wv1, const float* __restrict__ wo1,
                       const float* __restrict__ wvh, const float* __restrict__ wo2,
                       const float* __restrict__ wff1, const float* __restrict__ wff2,
                       const float* __restrict__ bff1) {
    int idx = blockIdx.x * 256 + threadIdx.x;
    if (idx < 102400) {
        int n = idx % 320, k = idx / 320;
        float s = 0.0f;
        for (int j = 0; j < 320; j++) s += wvh[k * 320 + j] * wo2[j * 320 + n];
        g_w2t[n * 320 + k] = __float2bfloat16(s);
    } else if (idx < 204800) {
        int i = idx - 102400; int n = i / 320, k = i % 320;
        g_wqkvt[i] = __float2bfloat16(wq1[k * 320 + n]);
    } else if (idx < 307200) {
        int i = idx - 204800; int n = i / 320, k = i % 320;
        g_wqkvt[102400 + i] = __float2bfloat16(wk1[k * 320 + n]);
    } else if (idx < 409600) {
        int i = idx - 307200; int n = i / 320, k = i % 320;
        g_wqkvt[204800 + i] = __float2bfloat16(wv1[k * 320 + n]);
    } else if (idx < 512000) {
        int i = idx - 409600; int n = i / 320, k = i % 320;
        g_wo1t[i] = __float2bfloat16(wo1[k * 320 + n]);
    } else if (idx < 921600) {
        int i = idx - 512000; int n = i / 1280, k = i % 1280;
        g_wff2t[i] = __float2bfloat16(wff2[k * 320 + n]);
    } else if (idx < 1740800) {
        int i = idx - 921600; int c = i / 320, k = i % 320;
        int j = (c >> 1) + (c & 1) * FFD;
        g_wff1t[i] = __float2bfloat16(wff1[(size_t)k * 2 * FFD + j]);
    } else if (idx < 1743360) {
        int c = idx - 1740800;
        g_bffi[c] = bff1[(c >> 1) + (c & 1) * FFD];
    }
}

// ---------------- Launch ----------------
extern "C" void kernel_launch(void* const* d_in, const int* in_sizes, int n_in,
                              void* d_out, int out_size) {
    (void)in_sizes; (void)n_in; (void)out_size;
    const float* hidden = (const float*)d_in[0];
    const float* ln1_g = (const float*)d_in[2];
    const float* ln1_b = (const float*)d_in[3];
    const float* wq1   = (const float*)d_in[4];
    const float* wk1   = (const float*)d_in[5];
    const float* wv1   = (const float*)d_in[6];
    const float* wo1   = (const float*)d_in[7];
    const float* bo1   = (const float*)d_in[8];
    const float* ln2_g = (const float*)d_in[9];
    const float* ln2_b = (const float*)d_in[10];
    const float* wvh   = (const float*)d_in[13];
    const float* wo2   = (const float*)d_in[14];
    const float* bo2   = (const float*)d_in[15];
    const float* ln3_g = (const float*)d_in[16];
    const float* ln3_b = (const float*)d_in[17];
    const float* wff1  = (const float*)d_in[18];
    const float* bff1  = (const float*)d_in[19];
    const float* wff2  = (const float*)d_in[20];
    const float* bff2  = (const float*)d_in[21];
    float* out = (float*)d_out;

    bf16 *s_lnb, *s_qkv, *s_attn, *s_ffin;
    bf16 *s_wqkvt, *s_wo1t, *s_w2t, *s_wff1t, *s_wff2t;
    float *s_res, *s_res2, *s_bffi;
    cudaGetSymbolAddress((void**)&s_lnb, g_lnb);
    cudaGetSymbolAddress((void**)&s_qkv, g_qkv);
    cudaGetSymbolAddress((void**)&s_attn, g_attn);
    cudaGetSymbolAddress((void**)&s_res, g_res);
    cudaGetSymbolAddress((void**)&s_res2, g_res2);
    cudaGetSymbolAddress((void**)&s_ffin, g_ffin);
    cudaGetSymbolAddress((void**)&s_wqkvt, g_wqkvt);
    cudaGetSymbolAddress((void**)&s_wo1t, g_wo1t);
    cudaGetSymbolAddress((void**)&s_w2t, g_w2t);
    cudaGetSymbolAddress((void**)&s_wff1t, g_wff1t);
    cudaGetSymbolAddress((void**)&s_wff2t, g_wff2t);
    cudaGetSymbolAddress((void**)&s_bffi, g_bffi);

    cudaFuncSetAttribute(flash_k, cudaFuncAttributeMaxDynamicSharedMemorySize, FL_SMEM);

    GP p{};

    // 1. weight prep
    prep_k<<<(1743360 + 255) / 256, 256>>>(wq1, wk1, wv1, wo1, wvh, wo2, wff1, wff2, bff1);

    // 2. LN1 + fused QKV GEMM
    ln_k<<<NROWS, DIM>>>(hidden, ln1_g, ln1_b, s_lnb);
    p = GP{ s_lnb, DIM,  s_wqkvt, DIM, QKVN,
            nullptr, s_qkv, QKVN,  nullptr, nullptr, NROWS, QKVN, DIM };
    gemm_k<1, 128><<<dim3(8, 32), 256>>>(p);

    // 3. fused flash attention
    flash_k<<<dim3(LQ / 128, BH), 256, FL_SMEM>>>(s_qkv, s_attn);

    // 4. wo1 + bias + residual
    p = GP{ s_attn, DIM,  s_wo1t, DIM, DIM,
            s_res, nullptr, DIM,  bo1, hidden, NROWS, DIM, DIM };
    gemm_k<0, 64><<<dim3(5, 32), 256>>>(p);

    // 5. LN2 + folded cross-attn + residual
    ln_k<<<NROWS, DIM>>>(s_res, ln2_g, ln2_b, s_lnb);
    p = GP{ s_lnb, DIM,  s_w2t, DIM, DIM,
            s_res2, nullptr, DIM,  bo2, s_res, NROWS, DIM, DIM };
    gemm_k<0, 64><<<dim3(5, 32), 256>>>(p);

    // 6. LN3 + FF1 (fused GEGLU) + FF2 + residual
    ln_k<<<NROWS, DIM>>>(s_res2, ln3_g, ln3_b, s_lnb);
    p = GP{ s_lnb, DIM,  s_wff1t, DIM, 2 * FFD,
            nullptr, s_ffin, FFD,  s_bffi, nullptr, NROWS, 2 * FFD, DIM };
    gemm_k<3, 128><<<dim3(20, 32), 256>>>(p);
    p = GP{ s_ffin, FFD,  s_wff2t, FFD, DIM,
            out, nullptr, DIM,  bff2, s_res2, NROWS, DIM, FFD };
    gemm_k<0, 64><<<dim3(5, 32), 256>>>(p);
}

// round 7
// speedup vs baseline: 1.1951x; 1.0932x over previous
#include <cuda_runtime.h>
#include <cuda_bf16.h>
#include <math.h>
#include <stdint.h>

// ---------------- Problem constants ----------------
#define NB     2
#define LQ     2048
#define DIM    320
#define NH     8
#define HD     40
#define BH     (NB * NH)         // 16
#define NROWS  (NB * LQ)         // 4096
#define FFD    1280
#define QKVN   960

typedef __nv_bfloat16 bf16;

// ---------------- Static scratch ----------------
__device__ bf16  g_lnb [NROWS * DIM];
__device__ bf16  g_qkv [NROWS * QKVN];
__device__ bf16  g_attn[NROWS * DIM];
__device__ float g_res [NROWS * DIM];
__device__ float g_res2[NROWS * DIM];
__device__ bf16  g_ffin[(size_t)NROWS * FFD];
__device__ bf16  g_wqkvt[QKVN * DIM];
__device__ bf16  g_wo1t [DIM * DIM];
__device__ bf16  g_w2t  [DIM * DIM];
__device__ bf16  g_wff1t[2 * FFD * DIM];   // interleaved: col 2j=x_j, 2j+1=gate_j
__device__ bf16  g_wff2t[DIM * FFD];
__device__ float g_bffi [2 * FFD];

// ---------------- Helpers ----------------
__device__ __forceinline__ uint32_t s2u(const void* p) {
    uint32_t a;
    asm("{ .reg .u64 t; cvta.to.shared.u64 t, %1; cvt.u32.u64 %0, t; }" : "=r"(a) : "l"(p));
    return a;
}
__device__ __forceinline__ void cpa16(uint32_t s, const void* g) {
    asm volatile("cp.async.cg.shared.global [%0], [%1], 16;\n" :: "r"(s), "l"(g));
}
__device__ __forceinline__ void cpa16z(uint32_t s, const void* g, int nb) {
    asm volatile("cp.async.cg.shared.global [%0], [%1], 16, %2;\n" :: "r"(s), "l"(g), "r"(nb));
}
__device__ __forceinline__ void cpa_commit() { asm volatile("cp.async.commit_group;\n" ::: "memory"); }
template<int N> __device__ __forceinline__ void cpa_wait() {
    asm volatile("cp.async.wait_group %0;\n" :: "n"(N) : "memory");
}
__device__ __forceinline__ void mma16816(float* d, const uint32_t* a, const uint32_t* b) {
    asm volatile("mma.sync.aligned.m16n8k16.row.col.f32.bf16.bf16.f32 "
        "{%0,%1,%2,%3}, {%4,%5,%6,%7}, {%8,%9}, {%0,%1,%2,%3};"
        : "+f"(d[0]), "+f"(d[1]), "+f"(d[2]), "+f"(d[3])
        : "r"(a[0]), "r"(a[1]), "r"(a[2]), "r"(a[3]), "r"(b[0]), "r"(b[1]));
}
__device__ __forceinline__ void ldm_x4(uint32_t* r, uint32_t addr) {
    asm volatile("ldmatrix.sync.aligned.m8n8.x4.shared.b16 {%0,%1,%2,%3}, [%4];"
        : "=r"(r[0]), "=r"(r[1]), "=r"(r[2]), "=r"(r[3]) : "r"(addr));
}
__device__ __forceinline__ void ldm_x4t(uint32_t* r, uint32_t addr) {
    asm volatile("ldmatrix.sync.aligned.m8n8.x4.trans.shared.b16 {%0,%1,%2,%3}, [%4];"
        : "=r"(r[0]), "=r"(r[1]), "=r"(r[2]), "=r"(r[3]) : "r"(addr));
}
// exp(v*scale) = ex2(v * (scale*log2e)) via MUFU
#define PRESCALE 0.22811011529542488f     // (1/sqrt(40)) * log2(e)
__device__ __forceinline__ float fex2(float x) {
    float r;
    asm("ex2.approx.f32 %0, %1;" : "=f"(r) : "f"(x));
    return r;
}
__device__ __forceinline__ uint32_t packbf2(float a, float b) {
    __nv_bfloat162 h = __floats2bfloat162_rn(a, b);
    return *(uint32_t*)&h;
}

// ---------------- GEMM: C[M,N] = A[M,K] @ B[N,K]^T ----------------
#define ASTRIDE 40

struct GP {
    const bf16* A; int lda;
    const bf16* B; int ldb, nB;
    float* Cf; bf16* Cb; int ldc;
    const float* bias; const float* res;
    int M, N, K;
};

// EPI: 0 = fp32 out (+bias?)(+res?), 1 = bf16 out, 3 = fused GEGLU (interleaved)
// BN: 128 (8 warps of 64x32) or 64 (8 warps of 32x32)
template<int EPI, int BN>
__global__ void __launch_bounds__(256, 2) gemm_k(GP p) {
    constexpr int MT = (BN == 128) ? 4 : 2;
    __shared__ bf16 sA[2][128 * ASTRIDE];
    __shared__ bf16 sB[2][BN * ASTRIDE];

    const int tid = threadIdx.x;
    const int wid = tid >> 5, lane = tid & 31;
    const int g = lane >> 2, t = lane & 3;
    const int wm = (BN == 128) ? (wid >> 2) * 64 : (wid >> 1) * 32;
    const int wn = (BN == 128) ? (wid & 3) * 32 : (wid & 1) * 32;
    const int n0 = blockIdx.x * BN, m0 = blockIdx.y * 128;
    const int arow = lane & 15, acol = (lane >> 4) << 3;
    const int brow = (lane & 7) + ((lane >> 4) << 3), bcol = ((lane >> 3) & 1) << 3;

    float acc[MT][4][4];
    #pragma unroll
    for (int i = 0; i < MT; i++)
        #pragma unroll
        for (int j = 0; j < 4; j++)
            #pragma unroll
            for (int q = 0; q < 4; q++) acc[i][j][q] = 0.0f;

    auto load_stage = [&](int ch, int st) {
        const int k0 = ch * 32;
        #pragma unroll
        for (int j = 0; j < 2; j++) {
            int id = tid + j * 256;
            int r = id >> 2, c = id & 3;
            cpa16(s2u(&sA[st][r * ASTRIDE + c * 8]),
                  p.A + (size_t)(m0 + r) * p.lda + k0 + c * 8);
        }
        #pragma unroll
        for (int j = 0; j < BN / 64; j++) {
            int id = tid + j * 256;
            int r = id >> 2, c = id & 3;
            int rn = n0 + r; if (rn >= p.nB) rn = p.nB - 1;
            cpa16(s2u(&sB[st][r * ASTRIDE + c * 8]),
                  p.B + (size_t)rn * p.ldb + k0 + c * 8);
        }
        cpa_commit();
    };

    auto compute_stage = [&](int st) {
        #pragma unroll
        for (int ks = 0; ks < 2; ks++) {
            uint32_t af[MT][4], bfr[4][2];
            #pragma unroll
            for (int mt = 0; mt < MT; mt++)
                ldm_x4(af[mt], s2u(&sA[st][(wm + mt * 16 + arow) * ASTRIDE + ks * 16 + acol]));
            #pragma unroll
            for (int pp = 0; pp < 2; pp++) {
                uint32_t r4[4];
                ldm_x4(r4, s2u(&sB[st][(wn + pp * 16 + brow) * ASTRIDE + ks * 16 + bcol]));
                bfr[2 * pp][0] = r4[0]; bfr[2 * pp][1] = r4[1];
                bfr[2 * pp + 1][0] = r4[2]; bfr[2 * pp + 1][1] = r4[3];
            }
            #pragma unroll
            for (int mt = 0; mt < MT; mt++)
                #pragma unroll
                for (int nt = 0; nt < 4; nt++)
                    mma16816(acc[mt][nt], af[mt], bfr[nt]);
        }
    };

    const int NC = p.K >> 5;
    load_stage(0, 0);
    for (int i = 0; i < NC; i++) {
        if (i + 1 < NC) { load_stage(i + 1, (i + 1) & 1); cpa_wait<1>(); }
        else            { cpa_wait<0>(); }
        __syncthreads();
        compute_stage(i & 1);
        __syncthreads();
    }

    #pragma unroll
    for (int mt = 0; mt < MT; mt++) {
        const int r0 = m0 + wm + mt * 16 + g;
        const int r1 = r0 + 8;
        #pragma unroll
        for (int nt = 0; nt < 4; nt++) {
            const int cb = n0 + wn + nt * 8;
            if (cb >= p.N) continue;
            const int c = cb + 2 * t;
            float v0 = acc[mt][nt][0], v1 = acc[mt][nt][1];
            float v2 = acc[mt][nt][2], v3 = acc[mt][nt][3];
            if (EPI == 3) {
                v0 += p.bias[c]; v1 += p.bias[c + 1];
                v2 += p.bias[c]; v3 += p.bias[c + 1];
                float o0 = v0 * 0.5f * v1 * (1.0f + erff(v1 * 0.7071067811865476f));
                float o1 = v2 * 0.5f * v3 * (1.0f + erff(v3 * 0.7071067811865476f));
                int j = c >> 1;
                p.Cb[(size_t)r0 * p.ldc + j] = __float2bfloat16(o0);
                p.Cb[(size_t)r1 * p.ldc + j] = __float2bfloat16(o1);
            } else if (EPI == 1) {
                *(uint32_t*)(p.Cb + (size_t)r0 * p.ldc + c) = packbf2(v0, v1);
                *(uint32_t*)(p.Cb + (size_t)r1 * p.ldc + c) = packbf2(v2, v3);
            } else {
                if (p.bias) {
                    float2 bb = *(const float2*)(p.bias + c);
                    v0 += bb.x; v1 += bb.y; v2 += bb.x; v3 += bb.y;
                }
                if (p.res) {
                    float2 q0 = *(const float2*)(p.res + (size_t)r0 * p.ldc + c);
                    float2 q1 = *(const float2*)(p.res + (size_t)r1 * p.ldc + c);
                    v0 += q0.x; v1 += q0.y; v2 += q1.x; v3 += q1.y;
                }
                *(float2*)(p.Cf + (size_t)r0 * p.ldc + c) = make_float2(v0, v1);
                *(float2*)(p.Cf + (size_t)r1 * p.ldc + c) = make_float2(v2, v3);
            }
        }
    }
}

// ---------------- Fused flash attention (v3: MUFU exp + MMA rowsum) ----------
#define KSTR 56
#define VSTR 56
#define FL_SMEM (2 * 128 * KSTR * 2 + 2 * 128 * VSTR * 2)   // 57344 B

__global__ void __launch_bounds__(256, 2) flash_k(const bf16* __restrict__ qkv,
                                                  bf16* __restrict__ attn) {
    extern __shared__ bf16 fsm[];
    bf16* sK = fsm;                      // [2][128*KSTR]
    bf16* sV = fsm + 2 * 128 * KSTR;     // [2][128*VSTR]

    const int tid = threadIdx.x, wid = tid >> 5, lane = tid & 31;
    const int g = lane >> 2, t = lane & 3;
    const int z = blockIdx.y, b = z >> 3, h = z & 7;
    const int m0 = blockIdx.x * 128;

    // ldmatrix lane mappings
    const int lrow = (lane & 7) + ((lane >> 4) << 3);         // K (non-trans x4)
    const int lcol = ((lane >> 3) & 1) << 3;
    const int vlrow = (lane & 7) + (((lane >> 3) & 1) << 3);  // V (trans)
    const int vcol = (lane >> 4) << 3;

    // ones in V cols 40..47 (both stages) -> rowsum via 6th PV n-tile.
    // cp.async only ever writes cols 0..39, so this survives the mainloop.
    #pragma unroll
    for (int j = 0; j < 4; j++) {
        int id = tid + j * 256;            // 0..1023
        int stg = id >> 9;
        int r = (id >> 2) & 127;
        int c = id & 3;
        *(uint32_t*)(sV + stg * 128 * VSTR + r * VSTR + 40 + c * 2) = 0x3F803F80u;
    }

    // Q fragments (d = 0..47; cols 40..47 zero)
    uint32_t qf[3][4];
    {
        const bf16* qb = qkv + (size_t)(b * LQ + m0 + wid * 16) * QKVN + h * HD;
        #pragma unroll
        for (int ks = 0; ks < 3; ks++) {
            int c0 = ks * 16 + 2 * t;
            qf[ks][0] = *(const uint32_t*)(qb + (size_t)g * QKVN + c0);
            qf[ks][1] = *(const uint32_t*)(qb + (size_t)(g + 8) * QKVN + c0);
            if (ks < 2) {
                qf[ks][2] = *(const uint32_t*)(qb + (size_t)g * QKVN + c0 + 8);
                qf[ks][3] = *(const uint32_t*)(qb + (size_t)(g + 8) * QKVN + c0 + 8);
            } else { qf[ks][2] = 0u; qf[ks][3] = 0u; }
        }
    }

    auto loadKV = [&](int kt, int st) {
        #pragma unroll
        for (int j = 0; j < 3; j++) {          // K: 128 rows x 6 chunks (5 real + zfill)
            int id = tid + j * 256;
            int r = id / 6, c = id % 6;
            uint32_t so = s2u(sK + st * 128 * KSTR + r * KSTR + c * 8);
            const bf16* gp = qkv + (size_t)(b * LQ + kt * 128 + r) * QKVN + DIM + h * HD + c * 8;
            cpa16z(so, gp, c < 5 ? 16 : 0);
        }
        #pragma unroll
        for (int j = 0; j < 3; j++) {          // V: 128 rows x 5 chunks (natural layout)
            int id = tid + j * 256;
            if (id < 640) {
                int r = id / 5, c = id % 5;
                uint32_t so = s2u(sV + st * 128 * VSTR + r * VSTR + c * 8);
                const bf16* gp = qkv + (size_t)(b * LQ + kt * 128 + r) * QKVN + 2 * DIM + h * HD + c * 8;
                cpa16(so, gp);
            }
        }
        cpa_commit();
    };

    float accO[6][4];
    #pragma unroll
    for (int i = 0; i < 6; i++)
        #pragma unroll
        for (int q = 0; q < 4; q++) accO[i][q] = 0.0f;

    auto compute = [&](int st) {
        const bf16* kb = sK + st * 128 * KSTR;
        const bf16* vb = sV + st * 128 * VSTR;
        #pragma unroll
        for (int half = 0; half < 2; half++) {
            // ---- S half = Q @ K^T (64 cols) ----
            float accS[8][4];
            #pragma unroll
            for (int i = 0; i < 8; i++)
                #pragma unroll
                for (int q = 0; q < 4; q++) accS[i][q] = 0.0f;
            #pragma unroll
            for (int ks = 0; ks < 3; ks++) {
                #pragma unroll
                for (int pair = 0; pair < 4; pair++) {
                    uint32_t r4[4];
                    ldm_x4(r4, s2u(kb + (half * 64 + pair * 16 + lrow) * KSTR + ks * 16 + lcol));
                    mma16816(accS[2 * pair], qf[ks], r4);
                    mma16816(accS[2 * pair + 1], qf[ks], r4 + 2);
                }
            }
            // ---- P = ex2(S*prescale) -> A-frags (MUFU) ----
            uint32_t pf[4][4];
            #pragma unroll
            for (int ks2 = 0; ks2 < 4; ks2++) {
                float e0 = fex2(accS[2 * ks2][0] * PRESCALE), e1 = fex2(accS[2 * ks2][1] * PRESCALE);
                float e2 = fex2(accS[2 * ks2][2] * PRESCALE), e3 = fex2(accS[2 * ks2][3] * PRESCALE);
                float f0 = fex2(accS[2 * ks2 + 1][0] * PRESCALE), f1 = fex2(accS[2 * ks2 + 1][1] * PRESCALE);
                float f2 = fex2(accS[2 * ks2 + 1][2] * PRESCALE), f3 = fex2(accS[2 * ks2 + 1][3] * PRESCALE);
                pf[ks2][0] = packbf2(e0, e1);
                pf[ks2][1] = packbf2(e2, e3);
                pf[ks2][2] = packbf2(f0, f1);
                pf[ks2][3] = packbf2(f2, f3);
            }
            // ---- O += P @ [V | 1] : 6 n-tiles, tile 5 = rowsum ----
            #pragma unroll
            for (int ks2 = 0; ks2 < 4; ks2++) {
                const int vrow = half * 64 + ks2 * 16 + vlrow;
                uint32_t bb[6][2];
                #pragma unroll
                for (int pp = 0; pp < 3; pp++) {
                    uint32_t r4[4];
                    ldm_x4t(r4, s2u(vb + vrow * VSTR + pp * 16 + vcol));
                    bb[2 * pp][0] = r4[0]; bb[2 * pp][1] = r4[1];
                    bb[2 * pp + 1][0] = r4[2]; bb[2 * pp + 1][1] = r4[3];
                }
                #pragma unroll
                for (int nt = 0; nt < 6; nt++)
                    mma16816(accO[nt], pf[ks2], bb[nt]);
            }
        }
    };

    loadKV(0, 0);
    #pragma unroll 1
    for (int kt2 = 0; kt2 < 8; kt2++) {
        // tile 2*kt2 (stage 0)
        loadKV(2 * kt2 + 1, 1);
        cpa_wait<1>();
        __syncthreads();
        compute(0);
        __syncthreads();
        // tile 2*kt2+1 (stage 1)
        if (kt2 < 7) { loadKV(2 * kt2 + 2, 0); cpa_wait<1>(); }
        else         { cpa_wait<0>(); }
        __syncthreads();
        compute(1);
        __syncthreads();
    }

    // ---- normalize (rowsum = accO[5]) + write ----
    const float i0 = 1.0f / accO[5][0], i1 = 1.0f / accO[5][2];
    const int r0 = b * LQ + m0 + wid * 16 + g, r1 = r0 + 8;
    #pragma unroll
    for (int nt = 0; nt < 5; nt++) {
        int col = h * HD + nt * 8 + 2 * t;
        *(uint32_t*)(attn + (size_t)r0 * DIM + col) = packbf2(accO[nt][0] * i0, accO[nt][1] * i0);
        *(uint32_t*)(attn + (size_t)r1 * DIM + col) = packbf2(accO[nt][2] * i1, accO[nt][3] * i1);
    }
}

// ---------------- LayerNorm (fp32 in -> bf16 out) ----------------
__global__ void ln_k(const float* __restrict__ x, const float* __restrict__ g,
                     const float* __restrict__ b, bf16* __restrict__ y) {
    __shared__ float red[32];
    int row = blockIdx.x, tid = threadIdx.x;
    float v = x[row * DIM + tid];
    float s = v;
    #pragma unroll
    for (int o = 16; o > 0; o >>= 1) s += __shfl_xor_sync(0xffffffffu, s, o);
    if ((tid & 31) == 0) red[tid >> 5] = s;
    __syncthreads();
    if (tid < 32) {
        float t2 = (tid < (DIM / 32)) ? red[tid] : 0.0f;
        #pragma unroll
        for (int o = 16; o > 0; o >>= 1) t2 += __shfl_xor_sync(0xffffffffu, t2, o);
        if (tid == 0) red[0] = t2;
    }
    __syncthreads();
    float mean = red[0] * (1.0f / DIM);
    __syncthreads();
    float d = v - mean;
    float s2 = d * d;
    #pragma unroll
    for (int o = 16; o > 0; o >>= 1) s2 += __shfl_xor_sync(0xffffffffu, s2, o);
    if ((tid & 31) == 0) red[tid >> 5] = s2;
    __syncthreads();
    if (tid < 32) {
        float t2 = (tid < (DIM / 32)) ? red[tid] : 0.0f;
        #pragma unroll
        for (int o = 16; o > 0; o >>= 1) t2 += __shfl_xor_sync(0xffffffffu, t2, o);
        if (tid == 0) red[0] = t2;
    }
    __syncthreads();
    float var = red[0] * (1.0f / DIM);
    y[row * DIM + tid] = __float2bfloat16(d * rsqrtf(var + 1e-5f) * g[tid] + b[tid]);
}

// ---------------- Merged prep ----------------
__global__ void prep_k(const float* __restrict__ wq1, const float* __restrict__ wk1,
                       const float* __restrict__ wv1, const float* __restrict__ wo1,
                       const float* __restrict__ wvh, const float* __restrict__ wo2,
                       const float* __restrict__ wff1, const float* __restrict__ wff2,
                       const float* __restrict__ bff1) {
    int idx = blockIdx.x * 256 + threadIdx.x;
    if (idx < 102400) {
        int n = idx % 320, k = idx / 320;
        float s = 0.0f;
        for (int j = 0; j < 320; j++) s += wvh[k * 320 + j] * wo2[j * 320 + n];
        g_w2t[n * 320 + k] = __float2bfloat16(s);
    } else if (idx < 204800) {
        int i = idx - 102400; int n = i / 320, k = i % 320;
        g_wqkvt[i] = __float2bfloat16(wq1[k * 320 + n]);
    } else if (idx < 307200) {
        int i = idx - 204800; int n = i / 320, k = i % 320;
        g_wqkvt[102400 + i] = __float2bfloat16(wk1[k * 320 + n]);
    } else if (idx < 409600) {
        int i = idx - 307200; int n = i / 320, k = i % 320;
        g_wqkvt[204800 + i] = __float2bfloat16(wv1[k * 320 + n]);
    } else if (idx < 512000) {
        int i = idx - 409600; int n = i / 320, k = i % 320;
        g_wo1t[i] = __float2bfloat16(wo1[k * 320 + n]);
    } else if (idx < 921600) {
        int i = idx - 512000; int n = i / 1280, k = i % 1280;
        g_wff2t[i] = __float2bfloat16(wff2[k * 320 + n]);
    } else if (idx < 1740800) {
        int i = idx - 921600; int c = i / 320, k = i % 320;
        int j = (c >> 1) + (c & 1) * FFD;
        g_wff1t[i] = __float2bfloat16(wff1[(size_t)k * 2 * FFD + j]);
    } else if (idx < 1743360) {
        int c = idx - 1740800;
        g_bffi[c] = bff1[(c >> 1) + (c & 1) * FFD];
    }
}

// ---------------- Launch ----------------
extern "C" void kernel_launch(void* const* d_in, const int* in_sizes, int n_in,
                              void* d_out, int out_size) {
    (void)in_sizes; (void)n_in; (void)out_size;
    const float* hidden = (const float*)d_in[0];
    const float* ln1_g = (const float*)d_in[2];
    const float* ln1_b = (const float*)d_in[3];
    const float* wq1   = (const float*)d_in[4];
    const float* wk1   = (const float*)d_in[5];
    const float* wv1   = (const float*)d_in[6];
    const float* wo1   = (const float*)d_in[7];
    const float* bo1   = (const float*)d_in[8];
    const float* ln2_g = (const float*)d_in[9];
    const float* ln2_b = (const float*)d_in[10];
    const float* wvh   = (const float*)d_in[13];
    const float* wo2   = (const float*)d_in[14];
    const float* bo2   = (const float*)d_in[15];
    const float* ln3_g = (const float*)d_in[16];
    const float* ln3_b = (const float*)d_in[17];
    const float* wff1  = (const float*)d_in[18];
    const float* bff1  = (const float*)d_in[19];
    const float* wff2  = (const float*)d_in[20];
    const float* bff2  = (const float*)d_in[21];
    float* out = (float*)d_out;

    bf16 *s_lnb, *s_qkv, *s_attn, *s_ffin;
    bf16 *s_wqkvt, *s_wo1t, *s_w2t, *s_wff1t, *s_wff2t;
    float *s_res, *s_res2, *s_bffi;
    cudaGetSymbolAddress((void**)&s_lnb, g_lnb);
    cudaGetSymbolAddress((void**)&s_qkv, g_qkv);
    cudaGetSymbolAddress((void**)&s_attn, g_attn);
    cudaGetSymbolAddress((void**)&s_res, g_res);
    cudaGetSymbolAddress((void**)&s_res2, g_res2);
    cudaGetSymbolAddress((void**)&s_ffin, g_ffin);
    cudaGetSymbolAddress((void**)&s_wqkvt, g_wqkvt);
    cudaGetSymbolAddress((void**)&s_wo1t, g_wo1t);
    cudaGetSymbolAddress((void**)&s_w2t, g_w2t);
    cudaGetSymbolAddress((void**)&s_wff1t, g_wff1t);
    cudaGetSymbolAddress((void**)&s_wff2t, g_wff2t);
    cudaGetSymbolAddress((void**)&s_bffi, g_bffi);

    cudaFuncSetAttribute(flash_k, cudaFuncAttributeMaxDynamicSharedMemorySize, FL_SMEM);

    GP p{};

    // 1. weight prep
    prep_k<<<(1743360 + 255) / 256, 256>>>(wq1, wk1, wv1, wo1, wvh, wo2, wff1, wff2, bff1);

    // 2. LN1 + fused QKV GEMM
    ln_k<<<NROWS, DIM>>>(hidden, ln1_g, ln1_b, s_lnb);
    p = GP{ s_lnb, DIM,  s_wqkvt, DIM, QKVN,
            nullptr, s_qkv, QKVN,  nullptr, nullptr, NROWS, QKVN, DIM };
    gemm_k<1, 128><<<dim3(8, 32), 256>>>(p);

    // 3. fused flash attention
    flash_k<<<dim3(LQ / 128, BH), 256, FL_SMEM>>>(s_qkv, s_attn);

    // 4. wo1 + bias + residual
    p = GP{ s_attn, DIM,  s_wo1t, DIM, DIM,
            s_res, nullptr, DIM,  bo1, hidden, NROWS, DIM, DIM };
    gemm_k<0, 64><<<dim3(5, 32), 256>>>(p);

    // 5. LN2 + folded cross-attn + residual
    ln_k<<<NROWS, DIM>>>(s_res, ln2_g, ln2_b, s_lnb);
    p = GP{ s_lnb, DIM,  s_w2t, DIM, DIM,
            s_res2, nullptr, DIM,  bo2, s_res, NROWS, DIM, DIM };
    gemm_k<0, 64><<<dim3(5, 32), 256>>>(p);

    // 6. LN3 + FF1 (fused GEGLU) + FF2 + residual
    ln_k<<<NROWS, DIM>>>(s_res2, ln3_g, ln3_b, s_lnb);
    p = GP{ s_lnb, DIM,  s_wff1t, DIM, 2 * FFD,
            nullptr, s_ffin, FFD,  s_bffi, nullptr, NROWS, 2 * FFD, DIM };
    gemm_k<3, 128><<<dim3(20, 32), 256>>>(p);
    p = GP{ s_ffin, FFD,  s_wff2t, FFD, DIM,
            out, nullptr, DIM,  bff2, s_res2, NROWS, DIM, FFD };
    gemm_k<0, 64><<<dim3(5, 32), 256>>>(p);
}

// round 8
// speedup vs baseline: 1.2285x; 1.0279x over previous
#include <cuda_runtime.h>
#include <cuda_bf16.h>
#include <math.h>
#include <stdint.h>

// ---------------- Problem constants ----------------
#define NB     2
#define LQ     2048
#define DIM    320
#define NH     8
#define HD     40
#define BH     (NB * NH)         // 16
#define NROWS  (NB * LQ)         // 4096
#define FFD    1280
#define QKVN   960

typedef __nv_bfloat16 bf16;

// ---------------- Static scratch ----------------
__device__ bf16  g_lnb [NROWS * DIM];
__device__ bf16  g_qkv [NROWS * QKVN];
__device__ bf16  g_attn[NROWS * DIM];
__device__ float g_res [NROWS * DIM];
__device__ float g_res2[NROWS * DIM];
__device__ bf16  g_ffin[(size_t)NROWS * FFD];
__device__ bf16  g_wqkvt[QKVN * DIM];
__device__ bf16  g_wo1t [DIM * DIM];
__device__ bf16  g_w2t  [DIM * DIM];
__device__ bf16  g_wff1t[2 * FFD * DIM];   // interleaved: col 2j=x_j, 2j+1=gate_j
__device__ bf16  g_wff2t[DIM * FFD];
__device__ float g_bffi [2 * FFD];

// ---------------- Helpers ----------------
__device__ __forceinline__ uint32_t s2u(const void* p) {
    uint32_t a;
    asm("{ .reg .u64 t; cvta.to.shared.u64 t, %1; cvt.u32.u64 %0, t; }" : "=r"(a) : "l"(p));
    return a;
}
__device__ __forceinline__ void cpa16(uint32_t s, const void* g) {
    asm volatile("cp.async.cg.shared.global [%0], [%1], 16;\n" :: "r"(s), "l"(g));
}
__device__ __forceinline__ void cpa16z(uint32_t s, const void* g, int nb) {
    asm volatile("cp.async.cg.shared.global [%0], [%1], 16, %2;\n" :: "r"(s), "l"(g), "r"(nb));
}
__device__ __forceinline__ void cpa_commit() { asm volatile("cp.async.commit_group;\n" ::: "memory"); }
template<int N> __device__ __forceinline__ void cpa_wait() {
    asm volatile("cp.async.wait_group %0;\n" :: "n"(N) : "memory");
}
__device__ __forceinline__ void mma16816(float* d, const uint32_t* a, const uint32_t* b) {
    asm volatile("mma.sync.aligned.m16n8k16.row.col.f32.bf16.bf16.f32 "
        "{%0,%1,%2,%3}, {%4,%5,%6,%7}, {%8,%9}, {%0,%1,%2,%3};"
        : "+f"(d[0]), "+f"(d[1]), "+f"(d[2]), "+f"(d[3])
        : "r"(a[0]), "r"(a[1]), "r"(a[2]), "r"(a[3]), "r"(b[0]), "r"(b[1]));
}
__device__ __forceinline__ void ldm_x4(uint32_t* r, uint32_t addr) {
    asm volatile("ldmatrix.sync.aligned.m8n8.x4.shared.b16 {%0,%1,%2,%3}, [%4];"
        : "=r"(r[0]), "=r"(r[1]), "=r"(r[2]), "=r"(r[3]) : "r"(addr));
}
__device__ __forceinline__ void ldm_x4t(uint32_t* r, uint32_t addr) {
    asm volatile("ldmatrix.sync.aligned.m8n8.x4.trans.shared.b16 {%0,%1,%2,%3}, [%4];"
        : "=r"(r[0]), "=r"(r[1]), "=r"(r[2]), "=r"(r[3]) : "r"(addr));
}
// exp(v*scale) = ex2(v * (scale*log2e)); scale prefolded into Q
#define PRESCALE 0.22811011529542488f     // (1/sqrt(40)) * log2(e)
__device__ __forceinline__ float fex2(float x) {
    float r;
    asm("ex2.approx.f32 %0, %1;" : "=f"(r) : "f"(x));
    return r;
}
__device__ __forceinline__ uint32_t packbf2(float a, float b) {
    __nv_bfloat162 h = __floats2bfloat162_rn(a, b);
    return *(uint32_t*)&h;
}

// ---------------- GEMM: C[M,N] = A[M,K] @ B[N,K]^T ----------------
#define ASTRIDE 40

struct GP {
    const bf16* A; int lda;
    const bf16* B; int ldb, nB;
    float* Cf; bf16* Cb; int ldc;
    const float* bias; const float* res;
    int M, N, K;
    float qs; int qsN;      // EPI1: scale cols < qsN by qs
};

// EPI: 0 = fp32 out (+bias?)(+res?), 1 = bf16 out (Q-prescale), 3 = fused GEGLU
// BN: 128 (8 warps of 64x32) or 64 (8 warps of 32x32)
template<int EPI, int BN>
__global__ void __launch_bounds__(256, 2) gemm_k(GP p) {
    constexpr int MT = (BN == 128) ? 4 : 2;
    constexpr uint32_t ATILE = 128 * ASTRIDE * 2;
    constexpr uint32_t BTILE = BN * ASTRIDE * 2;
    __shared__ bf16 sA[2][128 * ASTRIDE];
    __shared__ bf16 sB[2][BN * ASTRIDE];

    const int tid = threadIdx.x;
    const int wid = tid >> 5, lane = tid & 31;
    const int g = lane >> 2, t = lane & 3;
    const int wm = (BN == 128) ? (wid >> 2) * 64 : (wid >> 1) * 32;
    const int wn = (BN == 128) ? (wid & 3) * 32 : (wid & 1) * 32;
    const int n0 = blockIdx.x * BN, m0 = blockIdx.y * 128;
    const int arow = lane & 15, acol = (lane >> 4) << 3;
    const int brow = (lane & 7) + ((lane >> 4) << 3), bcol = ((lane >> 3) & 1) << 3;

    const uint32_t sAu = s2u(sA), sBu = s2u(sB);
    // per-thread invariant fragment offsets (bytes)
    const uint32_t aoff = ((wm + arow) * ASTRIDE + acol) * 2;
    const uint32_t boff = ((wn + brow) * ASTRIDE + bcol) * 2;
    // per-thread invariant store offsets (bytes)
    const int ldr = tid >> 2, ldc8 = (tid & 3) * 8;
    const uint32_t sAst = (ldr * ASTRIDE + ldc8) * 2;

    float acc[MT][4][4];
    #pragma unroll
    for (int i = 0; i < MT; i++)
        #pragma unroll
        for (int j = 0; j < 4; j++)
            #pragma unroll
            for (int q = 0; q < 4; q++) acc[i][j][q] = 0.0f;

    auto load_stage = [&](int ch, int st) {
        const int k0 = ch * 32;
        #pragma unroll
        for (int j = 0; j < 2; j++) {
            int r = ldr + j * 64;
            cpa16(sAu + st * ATILE + sAst + j * 64 * ASTRIDE * 2,
                  p.A + (size_t)(m0 + r) * p.lda + k0 + ldc8);
        }
        #pragma unroll
        for (int j = 0; j < BN / 64; j++) {
            int r = ldr + j * 64;
            int rn = n0 + r; if (rn >= p.nB) rn = p.nB - 1;
            cpa16(sBu + st * BTILE + sAst + j * 64 * ASTRIDE * 2,
                  p.B + (size_t)rn * p.ldb + k0 + ldc8);
        }
        cpa_commit();
    };

    auto compute_stage = [&](int st) {
        const uint32_t ab = sAu + st * ATILE + aoff;
        const uint32_t bb2 = sBu + st * BTILE + boff;
        #pragma unroll
        for (int ks = 0; ks < 2; ks++) {
            uint32_t af[MT][4], bfr[4][2];
            #pragma unroll
            for (int mt = 0; mt < MT; mt++)
                ldm_x4(af[mt], ab + mt * (16 * ASTRIDE * 2) + ks * 32);
            #pragma unroll
            for (int pp = 0; pp < 2; pp++) {
                uint32_t r4[4];
                ldm_x4(r4, bb2 + pp * (16 * ASTRIDE * 2) + ks * 32);
                bfr[2 * pp][0] = r4[0]; bfr[2 * pp][1] = r4[1];
                bfr[2 * pp + 1][0] = r4[2]; bfr[2 * pp + 1][1] = r4[3];
            }
            #pragma unroll
            for (int mt = 0; mt < MT; mt++)
                #pragma unroll
                for (int nt = 0; nt < 4; nt++)
                    mma16816(acc[mt][nt], af[mt], bfr[nt]);
        }
    };

    const int NC = p.K >> 5;
    load_stage(0, 0);
    for (int i = 0; i < NC; i++) {
        if (i + 1 < NC) { load_stage(i + 1, (i + 1) & 1); cpa_wait<1>(); }
        else            { cpa_wait<0>(); }
        __syncthreads();
        compute_stage(i & 1);
        __syncthreads();
    }

    #pragma unroll
    for (int mt = 0; mt < MT; mt++) {
        const int r0 = m0 + wm + mt * 16 + g;
        const int r1 = r0 + 8;
        #pragma unroll
        for (int nt = 0; nt < 4; nt++) {
            const int cb = n0 + wn + nt * 8;
            if (cb >= p.N) continue;
            const int c = cb + 2 * t;
            float v0 = acc[mt][nt][0], v1 = acc[mt][nt][1];
            float v2 = acc[mt][nt][2], v3 = acc[mt][nt][3];
            if (EPI == 3) {
                v0 += p.bias[c]; v1 += p.bias[c + 1];
                v2 += p.bias[c]; v3 += p.bias[c + 1];
                float o0 = v0 * 0.5f * v1 * (1.0f + erff(v1 * 0.7071067811865476f));
                float o1 = v2 * 0.5f * v3 * (1.0f + erff(v3 * 0.7071067811865476f));
                int j = c >> 1;
                p.Cb[(size_t)r0 * p.ldc + j] = __float2bfloat16(o0);
                p.Cb[(size_t)r1 * p.ldc + j] = __float2bfloat16(o1);
            } else if (EPI == 1) {
                float sc = (c < p.qsN) ? p.qs : 1.0f;
                *(uint32_t*)(p.Cb + (size_t)r0 * p.ldc + c) = packbf2(v0 * sc, v1 * sc);
                *(uint32_t*)(p.Cb + (size_t)r1 * p.ldc + c) = packbf2(v2 * sc, v3 * sc);
            } else {
                if (p.bias) {
                    float2 bb = *(const float2*)(p.bias + c);
                    v0 += bb.x; v1 += bb.y; v2 += bb.x; v3 += bb.y;
                }
                if (p.res) {
                    float2 q0 = *(const float2*)(p.res + (size_t)r0 * p.ldc + c);
                    float2 q1 = *(const float2*)(p.res + (size_t)r1 * p.ldc + c);
                    v0 += q0.x; v1 += q0.y; v2 += q1.x; v3 += q1.y;
                }
                *(float2*)(p.Cf + (size_t)r0 * p.ldc + c) = make_float2(v0, v1);
                *(float2*)(p.Cf + (size_t)r1 * p.ldc + c) = make_float2(v2, v3);
            }
        }
    }
}

// ---------------- Fused flash attention (v4: 32-bit addressing) ----------
#define KSTR 56
#define VSTR 56
#define KTILE (128 * KSTR * 2)
#define VTILE (128 * VSTR * 2)
#define FL_SMEM (2 * KTILE + 2 * VTILE)   // 57344 B

__global__ void __launch_bounds__(256, 2) flash_k(const bf16* __restrict__ qkv,
                                                  bf16* __restrict__ attn) {
    extern __shared__ bf16 fsm[];
    bf16* sV = fsm + 2 * 128 * KSTR;

    const int tid = threadIdx.x, wid = tid >> 5, lane = tid & 31;
    const int g = lane >> 2, t = lane & 3;
    const int z = blockIdx.y, b = z >> 3, h = z & 7;
    const int m0 = blockIdx.x * 128;

    const uint32_t sKu = s2u(fsm);
    const uint32_t sVu = sKu + 2 * KTILE;

    // ldmatrix lane-invariant byte offsets
    const int lrow = (lane & 7) + ((lane >> 4) << 3);         // K (non-trans x4)
    const int lcol = ((lane >> 3) & 1) << 3;
    const uint32_t koff = (lrow * KSTR + lcol) * 2;
    const int vlrow = (lane & 7) + (((lane >> 3) & 1) << 3);  // V (trans)
    const int vcol = (lane >> 4) << 3;
    const uint32_t voff = (vlrow * VSTR + vcol) * 2;

    // ones in V cols 40..47 (both stages) -> rowsum via 6th PV n-tile
    #pragma unroll
    for (int j = 0; j < 4; j++) {
        int id = tid + j * 256;
        int stg = id >> 9;
        int r = (id >> 2) & 127;
        int c = id & 3;
        *(uint32_t*)(sV + stg * 128 * VSTR + r * VSTR + 40 + c * 2) = 0x3F803F80u;
    }

    // Q fragments (prescaled by PRESCALE in QKV epilogue; cols 40..47 zero)
    uint32_t qf[3][4];
    {
        const bf16* qb = qkv + (size_t)(b * LQ + m0 + wid * 16) * QKVN + h * HD;
        #pragma unroll
        for (int ks = 0; ks < 3; ks++) {
            int c0 = ks * 16 + 2 * t;
            qf[ks][0] = *(const uint32_t*)(qb + (size_t)g * QKVN + c0);
            qf[ks][1] = *(const uint32_t*)(qb + (size_t)(g + 8) * QKVN + c0);
            if (ks < 2) {
                qf[ks][2] = *(const uint32_t*)(qb + (size_t)g * QKVN + c0 + 8);
                qf[ks][3] = *(const uint32_t*)(qb + (size_t)(g + 8) * QKVN + c0 + 8);
            } else { qf[ks][2] = 0u; qf[ks][3] = 0u; }
        }
    }

    // per-thread invariant load indices
    const int kr6 = tid / 6 * 0;  (void)kr6;

    auto loadKV = [&](int kt, int st) {
        const bf16* kbase = qkv + (size_t)(b * LQ + kt * 128) * QKVN + DIM + h * HD;
        #pragma unroll
        for (int j = 0; j < 3; j++) {          // K: 128 rows x 6 chunks (5 real + zfill)
            int id = tid + j * 256;
            int r = id / 6, c = id % 6;
            uint32_t so = sKu + st * KTILE + (r * KSTR + c * 8) * 2;
            cpa16z(so, kbase + (size_t)r * QKVN + c * 8, c < 5 ? 16 : 0);
        }
        const bf16* vbase = kbase + DIM;
        #pragma unroll
        for (int j = 0; j < 3; j++) {          // V: 128 rows x 5 chunks (natural layout)
            int id = tid + j * 256;
            if (id < 640) {
                int r = id / 5, c = id % 5;
                uint32_t so = sVu + st * VTILE + (r * VSTR + c * 8) * 2;
                cpa16(so, vbase + (size_t)r * QKVN + c * 8);
            }
        }
        cpa_commit();
    };

    float accO[6][4];
    #pragma unroll
    for (int i = 0; i < 6; i++)
        #pragma unroll
        for (int q = 0; q < 4; q++) accO[i][q] = 0.0f;

    auto compute = [&](int st) {
        const uint32_t kb = sKu + st * KTILE + koff;
        const uint32_t vb = sVu + st * VTILE + voff;
        #pragma unroll
        for (int half = 0; half < 2; half++) {
            // ---- S half = Q @ K^T (64 cols) ----
            float accS[8][4];
            #pragma unroll
            for (int i = 0; i < 8; i++)
                #pragma unroll
                for (int q = 0; q < 4; q++) accS[i][q] = 0.0f;
            #pragma unroll
            for (int ks = 0; ks < 3; ks++) {
                #pragma unroll
                for (int pair = 0; pair < 4; pair++) {
                    uint32_t r4[4];
                    ldm_x4(r4, kb + half * (64 * KSTR * 2) + pair * (16 * KSTR * 2) + ks * 32);
                    mma16816(accS[2 * pair], qf[ks], r4);
                    mma16816(accS[2 * pair + 1], qf[ks], r4 + 2);
                }
            }
            // ---- P = ex2(S) -> A-frags (MUFU) ----
            uint32_t pf[4][4];
            #pragma unroll
            for (int ks2 = 0; ks2 < 4; ks2++) {
                float e0 = fex2(accS[2 * ks2][0]), e1 = fex2(accS[2 * ks2][1]);
                float e2 = fex2(accS[2 * ks2][2]), e3 = fex2(accS[2 * ks2][3]);
                float f0 = fex2(accS[2 * ks2 + 1][0]), f1 = fex2(accS[2 * ks2 + 1][1]);
                float f2 = fex2(accS[2 * ks2 + 1][2]), f3 = fex2(accS[2 * ks2 + 1][3]);
                pf[ks2][0] = packbf2(e0, e1);
                pf[ks2][1] = packbf2(e2, e3);
                pf[ks2][2] = packbf2(f0, f1);
                pf[ks2][3] = packbf2(f2, f3);
            }
            // ---- O += P @ [V | 1] : 6 n-tiles, tile 5 = rowsum ----
            #pragma unroll
            for (int ks2 = 0; ks2 < 4; ks2++) {
                const uint32_t vr = vb + half * (64 * VSTR * 2) + ks2 * (16 * VSTR * 2);
                uint32_t bb[6][2];
                #pragma unroll
                for (int pp = 0; pp < 3; pp++) {
                    uint32_t r4[4];
                    ldm_x4t(r4, vr + pp * 32);
                    bb[2 * pp][0] = r4[0]; bb[2 * pp][1] = r4[1];
                    bb[2 * pp + 1][0] = r4[2]; bb[2 * pp + 1][1] = r4[3];
                }
                #pragma unroll
                for (int nt = 0; nt < 6; nt++)
                    mma16816(accO[nt], pf[ks2], bb[nt]);
            }
        }
    };

    loadKV(0, 0);
    #pragma unroll 1
    for (int kt2 = 0; kt2 < 8; kt2++) {
        loadKV(2 * kt2 + 1, 1);
        cpa_wait<1>();
        __syncthreads();
        compute(0);
        __syncthreads();
        if (kt2 < 7) { loadKV(2 * kt2 + 2, 0); cpa_wait<1>(); }
        else         { cpa_wait<0>(); }
        __syncthreads();
        compute(1);
        __syncthreads();
    }

    // ---- normalize (rowsum = accO[5]) + write ----
    const float i0 = 1.0f / accO[5][0], i1 = 1.0f / accO[5][2];
    const int r0 = b * LQ + m0 + wid * 16 + g, r1 = r0 + 8;
    #pragma unroll
    for (int nt = 0; nt < 5; nt++) {
        int col = h * HD + nt * 8 + 2 * t;
        *(uint32_t*)(attn + (size_t)r0 * DIM + col) = packbf2(accO[nt][0] * i0, accO[nt][1] * i0);
        *(uint32_t*)(attn + (size_t)r1 * DIM + col) = packbf2(accO[nt][2] * i1, accO[nt][3] * i1);
    }
}

// ---------------- LayerNorm (fp32 in -> bf16 out) ----------------
__global__ void ln_k(const float* __restrict__ x, const float* __restrict__ g,
                     const float* __restrict__ b, bf16* __restrict__ y) {
    __shared__ float red[32];
    int row = blockIdx.x, tid = threadIdx.x;
    float v = x[row * DIM + tid];
    float s = v;
    #pragma unroll
    for (int o = 16; o > 0; o >>= 1) s += __shfl_xor_sync(0xffffffffu, s, o);
    if ((tid & 31) == 0) red[tid >> 5] = s;
    __syncthreads();
    if (tid < 32) {
        float t2 = (tid < (DIM / 32)) ? red[tid] : 0.0f;
        #pragma unroll
        for (int o = 16; o > 0; o >>= 1) t2 += __shfl_xor_sync(0xffffffffu, t2, o);
        if (tid == 0) red[0] = t2;
    }
    __syncthreads();
    float mean = red[0] * (1.0f / DIM);
    __syncthreads();
    float d = v - mean;
    float s2 = d * d;
    #pragma unroll
    for (int o = 16; o > 0; o >>= 1) s2 += __shfl_xor_sync(0xffffffffu, s2, o);
    if ((tid & 31) == 0) red[tid >> 5] = s2;
    __syncthreads();
    if (tid < 32) {
        float t2 = (tid < (DIM / 32)) ? red[tid] : 0.0f;
        #pragma unroll
        for (int o = 16; o > 0; o >>= 1) t2 += __shfl_xor_sync(0xffffffffu, t2, o);
        if (tid == 0) red[0] = t2;
    }
    __syncthreads();
    float var = red[0] * (1.0f / DIM);
    y[row * DIM + tid] = __float2bfloat16(d * rsqrtf(var + 1e-5f) * g[tid] + b[tid]);
}

// ---------------- Merged prep ----------------
__global__ void prep_k(const float* __restrict__ wq1, const float* __restrict__ wk1,
                       const float* __restrict__ wv1, const float* __restrict__ wo1,
                       const float* __restrict__ wvh, const float* __restrict__ wo2,
                       const float* __restrict__ wff1, const float* __restrict__ wff2,
                       const float* __restrict__ bff1) {
    int idx = blockIdx.x * 256 + threadIdx.x;
    if (idx < 102400) {
        int n = idx % 320, k = idx / 320;
        float s = 0.0f;
        for (int j = 0; j < 320; j++) s += wvh[k * 320 + j] * wo2[j * 320 + n];
        g_w2t[n * 320 + k] = __float2bfloat16(s);
    } else if (idx < 204800) {
        int i = idx - 102400; int n = i / 320, k = i % 320;
        g_wqkvt[i] = __float2bfloat16(wq1[k * 320 + n]);
    } else if (idx < 307200) {
        int i = idx - 204800; int n = i / 320, k = i % 320;
        g_wqkvt[102400 + i] = __float2bfloat16(wk1[k * 320 + n]);
    } else if (idx < 409600) {
        int i = idx - 307200; int n = i / 320, k = i % 320;
        g_wqkvt[204800 + i] = __float2bfloat16(wv1[k * 320 + n]);
    } else if (idx < 512000) {
        int i = idx - 409600; int n = i / 320, k = i % 320;
        g_wo1t[i] = __float2bfloat16(wo1[k * 320 + n]);
    } else if (idx < 921600) {
        int i = idx - 512000; int n = i / 1280, k = i % 1280;
        g_wff2t[i] = __float2bfloat16(wff2[k * 320 + n]);
    } else if (idx < 1740800) {
        int i = idx - 921600; int c = i / 320, k = i % 320;
        int j = (c >> 1) + (c & 1) * FFD;
        g_wff1t[i] = __float2bfloat16(wff1[(size_t)k * 2 * FFD + j]);
    } else if (idx < 1743360) {
        int c = idx - 1740800;
        g_bffi[c] = bff1[(c >> 1) + (c & 1) * FFD];
    }
}

// ---------------- Launch ----------------
extern "C" void kernel_launch(void* const* d_in, const int* in_sizes, int n_in,
                              void* d_out, int out_size) {
    (void)in_sizes; (void)n_in; (void)out_size;
    const float* hidden = (const float*)d_in[0];
    const float* ln1_g = (const float*)d_in[2];
    const float* ln1_b = (const float*)d_in[3];
    const float* wq1   = (const float*)d_in[4];
    const float* wk1   = (const float*)d_in[5];
    const float* wv1   = (const float*)d_in[6];
    const float* wo1   = (const float*)d_in[7];
    const float* bo1   = (const float*)d_in[8];
    const float* ln2_g = (const float*)d_in[9];
    const float* ln2_b = (const float*)d_in[10];
    const float* wvh   = (const float*)d_in[13];
    const float* wo2   = (const float*)d_in[14];
    const float* bo2   = (const float*)d_in[15];
    const float* ln3_g = (const float*)d_in[16];
    const float* ln3_b = (const float*)d_in[17];
    const float* wff1  = (const float*)d_in[18];
    const float* bff1  = (const float*)d_in[19];
    const float* wff2  = (const float*)d_in[20];
    const float* bff2  = (const float*)d_in[21];
    float* out = (float*)d_out;

    bf16 *s_lnb, *s_qkv, *s_attn, *s_ffin;
    bf16 *s_wqkvt, *s_wo1t, *s_w2t, *s_wff1t, *s_wff2t;
    float *s_res, *s_res2, *s_bffi;
    cudaGetSymbolAddress((void**)&s_lnb, g_lnb);
    cudaGetSymbolAddress((void**)&s_qkv, g_qkv);
    cudaGetSymbolAddress((void**)&s_attn, g_attn);
    cudaGetSymbolAddress((void**)&s_res, g_res);
    cudaGetSymbolAddress((void**)&s_res2, g_res2);
    cudaGetSymbolAddress((void**)&s_ffin, g_ffin);
    cudaGetSymbolAddress((void**)&s_wqkvt, g_wqkvt);
    cudaGetSymbolAddress((void**)&s_wo1t, g_wo1t);
    cudaGetSymbolAddress((void**)&s_w2t, g_w2t);
    cudaGetSymbolAddress((void**)&s_wff1t, g_wff1t);
    cudaGetSymbolAddress((void**)&s_wff2t, g_wff2t);
    cudaGetSymbolAddress((void**)&s_bffi, g_bffi);

    cudaFuncSetAttribute(flash_k, cudaFuncAttributeMaxDynamicSharedMemorySize, FL_SMEM);

    GP p{};

    // 1. weight prep
    prep_k<<<(1743360 + 255) / 256, 256>>>(wq1, wk1, wv1, wo1, wvh, wo2, wff1, wff2, bff1);

    // 2. LN1 + fused QKV GEMM (Q columns pre-scaled by PRESCALE)
    ln_k<<<NROWS, DIM>>>(hidden, ln1_g, ln1_b, s_lnb);
    p = GP{ s_lnb, DIM,  s_wqkvt, DIM, QKVN,
            nullptr, s_qkv, QKVN,  nullptr, nullptr, NROWS, QKVN, DIM,
            PRESCALE, DIM };
    gemm_k<1, 128><<<dim3(8, 32), 256>>>(p);

    // 3. fused flash attention
    flash_k<<<dim3(LQ / 128, BH), 256, FL_SMEM>>>(s_qkv, s_attn);

    // 4. wo1 + bias + residual
    p = GP{ s_attn, DIM,  s_wo1t, DIM, DIM,
            s_res, nullptr, DIM,  bo1, hidden, NROWS, DIM, DIM, 1.0f, 0 };
    gemm_k<0, 64><<<dim3(5, 32), 256>>>(p);

    // 5. LN2 + folded cross-attn + residual
    ln_k<<<NROWS, DIM>>>(s_res, ln2_g, ln2_b, s_lnb);
    p = GP{ s_lnb, DIM,  s_w2t, DIM, DIM,
            s_res2, nullptr, DIM,  bo2, s_res, NROWS, DIM, DIM, 1.0f, 0 };
    gemm_k<0, 64><<<dim3(5, 32), 256>>>(p);

    // 6. LN3 + FF1 (fused GEGLU) + FF2 + residual
    ln_k<<<NROWS, DIM>>>(s_res2, ln3_g, ln3_b, s_lnb);
    p = GP{ s_lnb, DIM,  s_wff1t, DIM, 2 * FFD,
            nullptr, s_ffin, FFD,  s_bffi, nullptr, NROWS, 2 * FFD, DIM, 1.0f, 0 };
    gemm_k<3, 128><<<dim3(20, 32), 256>>>(p);
    p = GP{ s_ffin, FFD,  s_wff2t, FFD, DIM,
            out, nullptr, DIM,  bff2, s_res2, NROWS, DIM, FFD, 1.0f, 0 };
    gemm_k<0, 64><<<dim3(5, 32), 256>>>(p);
}

// round 9
// speedup vs baseline: 1.3196x; 1.0742x over previous
#include <cuda_runtime.h>
#include <cuda_bf16.h>
#include <math.h>
#include <stdint.h>

// ---------------- Problem constants ----------------
#define NB     2
#define LQ     2048
#define DIM    320
#define NH     8
#define HD     40
#define BH     (NB * NH)         // 16
#define NROWS  (NB * LQ)         // 4096
#define FFD    1280
#define QKVN   960

typedef __nv_bfloat16 bf16;

// ---------------- Static scratch ----------------
__device__ bf16  g_lnb [NROWS * DIM];
__device__ bf16  g_qkv [NROWS * QKVN];
__device__ bf16  g_attn[NROWS * DIM];
__device__ float g_res [NROWS * DIM];
__device__ float g_res2[NROWS * DIM];
__device__ bf16  g_ffin[(size_t)NROWS * FFD];
__device__ bf16  g_wqkvt[QKVN * DIM];
__device__ bf16  g_wo1t [DIM * DIM];
__device__ bf16  g_w2t  [DIM * DIM];
__device__ bf16  g_wff1t[2 * FFD * DIM];   // interleaved: col 2j=x_j, 2j+1=gate_j
__device__ bf16  g_wff2t[DIM * FFD];
__device__ float g_bffi [2 * FFD];

// ---------------- Helpers ----------------
__device__ __forceinline__ uint32_t s2u(const void* p) {
    uint32_t a;
    asm("{ .reg .u64 t; cvta.to.shared.u64 t, %1; cvt.u32.u64 %0, t; }" : "=r"(a) : "l"(p));
    return a;
}
__device__ __forceinline__ void cpa16(uint32_t s, const void* g) {
    asm volatile("cp.async.cg.shared.global [%0], [%1], 16;\n" :: "r"(s), "l"(g));
}
__device__ __forceinline__ void cpa16z(uint32_t s, const void* g, int nb) {
    asm volatile("cp.async.cg.shared.global [%0], [%1], 16, %2;\n" :: "r"(s), "l"(g), "r"(nb));
}
__device__ __forceinline__ void cpa_commit() { asm volatile("cp.async.commit_group;\n" ::: "memory"); }
template<int N> __device__ __forceinline__ void cpa_wait() {
    asm volatile("cp.async.wait_group %0;\n" :: "n"(N) : "memory");
}
__device__ __forceinline__ void mma16816(float* d, const uint32_t* a, const uint32_t* b) {
    asm volatile("mma.sync.aligned.m16n8k16.row.col.f32.bf16.bf16.f32 "
        "{%0,%1,%2,%3}, {%4,%5,%6,%7}, {%8,%9}, {%0,%1,%2,%3};"
        : "+f"(d[0]), "+f"(d[1]), "+f"(d[2]), "+f"(d[3])
        : "r"(a[0]), "r"(a[1]), "r"(a[2]), "r"(a[3]), "r"(b[0]), "r"(b[1]));
}
__device__ __forceinline__ void ldm_x4(uint32_t* r, uint32_t addr) {
    asm volatile("ldmatrix.sync.aligned.m8n8.x4.shared.b16 {%0,%1,%2,%3}, [%4];"
        : "=r"(r[0]), "=r"(r[1]), "=r"(r[2]), "=r"(r[3]) : "r"(addr));
}
__device__ __forceinline__ void ldm_x4t(uint32_t* r, uint32_t addr) {
    asm volatile("ldmatrix.sync.aligned.m8n8.x4.trans.shared.b16 {%0,%1,%2,%3}, [%4];"
        : "=r"(r[0]), "=r"(r[1]), "=r"(r[2]), "=r"(r[3]) : "r"(addr));
}
// exp(v*scale) = ex2(v * (scale*log2e)); scale prefolded into Q
#define PRESCALE 0.22811011529542488f     // (1/sqrt(40)) * log2(e)
__device__ __forceinline__ float fex2(float x) {
    float r;
    asm("ex2.approx.f32 %0, %1;" : "=f"(r) : "f"(x));
    return r;
}
__device__ __forceinline__ uint32_t packbf2(float a, float b) {
    __nv_bfloat162 h = __floats2bfloat162_rn(a, b);
    return *(uint32_t*)&h;
}

// ---------------- GEMM: C[M,N] = A[M,K] @ B[N,K]^T ----------------
// 4-stage cp.async pipeline, 1 __syncthreads per K-chunk.
#define ASTRIDE 40

struct GP {
    const bf16* A; int lda;
    const bf16* B; int ldb, nB;
    float* Cf; bf16* Cb; int ldc;
    const float* bias; const float* res;
    int M, N, K;
    float qs; int qsN;      // EPI1: scale cols < qsN by qs
};

// EPI: 0 = fp32 out (+bias?)(+res?), 1 = bf16 out (Q-prescale), 3 = fused GEGLU
// BN: 128 (8 warps of 64x32) or 64 (8 warps of 32x32)
template<int EPI, int BN>
__global__ void __launch_bounds__(256, 2) gemm_k(GP p) {
    constexpr int MT = (BN == 128) ? 4 : 2;
    constexpr uint32_t ATILE = 128 * ASTRIDE * 2;   // 10240 B
    constexpr uint32_t BTILE = BN * ASTRIDE * 2;
    extern __shared__ bf16 gsm[];

    const int tid = threadIdx.x;
    const int wid = tid >> 5, lane = tid & 31;
    const int g = lane >> 2, t = lane & 3;
    const int wm = (BN == 128) ? (wid >> 2) * 64 : (wid >> 1) * 32;
    const int wn = (BN == 128) ? (wid & 3) * 32 : (wid & 1) * 32;
    const int n0 = blockIdx.x * BN, m0 = blockIdx.y * 128;
    const int arow = lane & 15, acol = (lane >> 4) << 3;
    const int brow = (lane & 7) + ((lane >> 4) << 3), bcol = ((lane >> 3) & 1) << 3;

    const uint32_t sAu = s2u(gsm);
    const uint32_t sBu = sAu + 4 * ATILE;
    const uint32_t aoff = ((wm + arow) * ASTRIDE + acol) * 2;
    const uint32_t boff = ((wn + brow) * ASTRIDE + bcol) * 2;
    const int ldr = tid >> 2, ldc8 = (tid & 3) * 8;
    const uint32_t sAst = (ldr * ASTRIDE + ldc8) * 2;

    float acc[MT][4][4];
    #pragma unroll
    for (int i = 0; i < MT; i++)
        #pragma unroll
        for (int j = 0; j < 4; j++)
            #pragma unroll
            for (int q = 0; q < 4; q++) acc[i][j][q] = 0.0f;

    auto load_stage = [&](int ch, int st) {
        const int k0 = ch * 32;
        #pragma unroll
        for (int j = 0; j < 2; j++) {
            int r = ldr + j * 64;
            cpa16(sAu + st * ATILE + sAst + j * 64 * ASTRIDE * 2,
                  p.A + (size_t)(m0 + r) * p.lda + k0 + ldc8);
        }
        #pragma unroll
        for (int j = 0; j < BN / 64; j++) {
            int r = ldr + j * 64;
            int rn = n0 + r; if (rn >= p.nB) rn = p.nB - 1;
            cpa16(sBu + st * BTILE + sAst + j * 64 * ASTRIDE * 2,
                  p.B + (size_t)rn * p.ldb + k0 + ldc8);
        }
        cpa_commit();
    };

    auto compute_stage = [&](int st) {
        const uint32_t ab = sAu + st * ATILE + aoff;
        const uint32_t bb2 = sBu + st * BTILE + boff;
        #pragma unroll
        for (int ks = 0; ks < 2; ks++) {
            uint32_t af[MT][4], bfr[4][2];
            #pragma unroll
            for (int mt = 0; mt < MT; mt++)
                ldm_x4(af[mt], ab + mt * (16 * ASTRIDE * 2) + ks * 32);
            #pragma unroll
            for (int pp = 0; pp < 2; pp++) {
                uint32_t r4[4];
                ldm_x4(r4, bb2 + pp * (16 * ASTRIDE * 2) + ks * 32);
                bfr[2 * pp][0] = r4[0]; bfr[2 * pp][1] = r4[1];
                bfr[2 * pp + 1][0] = r4[2]; bfr[2 * pp + 1][1] = r4[3];
            }
            #pragma unroll
            for (int mt = 0; mt < MT; mt++)
                #pragma unroll
                for (int nt = 0; nt < 4; nt++)
                    mma16816(acc[mt][nt], af[mt], bfr[nt]);
        }
    };

    const int NC = p.K >> 5;        // always >= 10 in our uses
    load_stage(0, 0);
    load_stage(1, 1);
    load_stage(2, 2);
    for (int i = 0; i < NC; i++) {
        if (i + 3 < NC)      cpa_wait<2>();
        else if (i + 2 < NC) cpa_wait<1>();
        else                 cpa_wait<0>();
        __syncthreads();
        if (i + 3 < NC) load_stage(i + 3, (i + 3) & 3);
        compute_stage(i & 3);
    }

    #pragma unroll
    for (int mt = 0; mt < MT; mt++) {
        const int r0 = m0 + wm + mt * 16 + g;
        const int r1 = r0 + 8;
        #pragma unroll
        for (int nt = 0; nt < 4; nt++) {
            const int cb = n0 + wn + nt * 8;
            if (cb >= p.N) continue;
            const int c = cb + 2 * t;
            float v0 = acc[mt][nt][0], v1 = acc[mt][nt][1];
            float v2 = acc[mt][nt][2], v3 = acc[mt][nt][3];
            if (EPI == 3) {
                v0 += p.bias[c]; v1 += p.bias[c + 1];
                v2 += p.bias[c]; v3 += p.bias[c + 1];
                float o0 = v0 * 0.5f * v1 * (1.0f + erff(v1 * 0.7071067811865476f));
                float o1 = v2 * 0.5f * v3 * (1.0f + erff(v3 * 0.7071067811865476f));
                int j = c >> 1;
                p.Cb[(size_t)r0 * p.ldc + j] = __float2bfloat16(o0);
                p.Cb[(size_t)r1 * p.ldc + j] = __float2bfloat16(o1);
            } else if (EPI == 1) {
                float sc = (c < p.qsN) ? p.qs : 1.0f;
                *(uint32_t*)(p.Cb + (size_t)r0 * p.ldc + c) = packbf2(v0 * sc, v1 * sc);
                *(uint32_t*)(p.Cb + (size_t)r1 * p.ldc + c) = packbf2(v2 * sc, v3 * sc);
            } else {
                if (p.bias) {
                    float2 bb = *(const float2*)(p.bias + c);
                    v0 += bb.x; v1 += bb.y; v2 += bb.x; v3 += bb.y;
                }
                if (p.res) {
                    float2 q0 = *(const float2*)(p.res + (size_t)r0 * p.ldc + c);
                    float2 q1 = *(const float2*)(p.res + (size_t)r1 * p.ldc + c);
                    v0 += q0.x; v1 += q0.y; v2 += q1.x; v3 += q1.y;
                }
                *(float2*)(p.Cf + (size_t)r0 * p.ldc + c) = make_float2(v0, v1);
                *(float2*)(p.Cf + (size_t)r1 * p.ldc + c) = make_float2(v2, v3);
            }
        }
    }
}
#define GEMM_SMEM_128 (4 * (128 * ASTRIDE * 2) * 2)            // 81920
#define GEMM_SMEM_64  (4 * (128 * ASTRIDE * 2) + 4 * (64 * ASTRIDE * 2))  // 61440

// ---------------- Fused flash attention (v5: 3-stage, 1 sync/tile) ----------
#define KSTR 56
#define VSTR 56
#define KTILE (128 * KSTR * 2)
#define VTILE (128 * VSTR * 2)
#define FL_SMEM (3 * KTILE + 3 * VTILE)   // 86016 B

__global__ void __launch_bounds__(256, 2) flash_k(const bf16* __restrict__ qkv,
                                                  bf16* __restrict__ attn) {
    extern __shared__ bf16 fsm[];
    bf16* sV = fsm + 3 * 128 * KSTR;

    const int tid = threadIdx.x, wid = tid >> 5, lane = tid & 31;
    const int g = lane >> 2, t = lane & 3;
    const int z = blockIdx.y, b = z >> 3, h = z & 7;
    const int m0 = blockIdx.x * 128;

    const uint32_t sKu = s2u(fsm);
    const uint32_t sVu = sKu + 3 * KTILE;

    // ldmatrix lane-invariant byte offsets
    const int lrow = (lane & 7) + ((lane >> 4) << 3);         // K (non-trans x4)
    const int lcol = ((lane >> 3) & 1) << 3;
    const uint32_t koff = (lrow * KSTR + lcol) * 2;
    const int vlrow = (lane & 7) + (((lane >> 3) & 1) << 3);  // V (trans)
    const int vcol = (lane >> 4) << 3;
    const uint32_t voff = (vlrow * VSTR + vcol) * 2;

    // ones in V cols 40..47 (all 3 stages) -> rowsum via 6th PV n-tile
    #pragma unroll
    for (int j = 0; j < 6; j++) {
        int id = tid + j * 256;            // 0..1535
        int stg = id / 512;
        int r = (id >> 2) & 127;
        int c = id & 3;
        *(uint32_t*)(sV + stg * 128 * VSTR + r * VSTR + 40 + c * 2) = 0x3F803F80u;
    }

    // Q fragments (prescaled by PRESCALE in QKV epilogue; cols 40..47 zero)
    uint32_t qf[3][4];
    {
        const bf16* qb = qkv + (size_t)(b * LQ + m0 + wid * 16) * QKVN + h * HD;
        #pragma unroll
        for (int ks = 0; ks < 3; ks++) {
            int c0 = ks * 16 + 2 * t;
            qf[ks][0] = *(const uint32_t*)(qb + (size_t)g * QKVN + c0);
            qf[ks][1] = *(const uint32_t*)(qb + (size_t)(g + 8) * QKVN + c0);
            if (ks < 2) {
                qf[ks][2] = *(const uint32_t*)(qb + (size_t)g * QKVN + c0 + 8);
                qf[ks][3] = *(const uint32_t*)(qb + (size_t)(g + 8) * QKVN + c0 + 8);
            } else { qf[ks][2] = 0u; qf[ks][3] = 0u; }
        }
    }

    auto loadKV = [&](int kt, int st) {
        const bf16* kbase = qkv + (size_t)(b * LQ + kt * 128) * QKVN + DIM + h * HD;
        #pragma unroll
        for (int j = 0; j < 3; j++) {          // K: 128 rows x 6 chunks (5 real + zfill)
            int id = tid + j * 256;
            int r = id / 6, c = id % 6;
            uint32_t so = sKu + st * KTILE + (r * KSTR + c * 8) * 2;
            cpa16z(so, kbase + (size_t)r * QKVN + c * 8, c < 5 ? 16 : 0);
        }
        const bf16* vbase = kbase + DIM;
        #pragma unroll
        for (int j = 0; j < 3; j++) {          // V: 128 rows x 5 chunks (natural layout)
            int id = tid + j * 256;
            if (id < 640) {
                int r = id / 5, c = id % 5;
                uint32_t so = sVu + st * VTILE + (r * VSTR + c * 8) * 2;
                cpa16(so, vbase + (size_t)r * QKVN + c * 8);
            }
        }
        cpa_commit();
    };

    float accO[6][4];
    #pragma unroll
    for (int i = 0; i < 6; i++)
        #pragma unroll
        for (int q = 0; q < 4; q++) accO[i][q] = 0.0f;

    auto compute = [&](int st) {
        const uint32_t kb = sKu + st * KTILE + koff;
        const uint32_t vb = sVu + st * VTILE + voff;
        #pragma unroll
        for (int half = 0; half < 2; half++) {
            // ---- S half = Q @ K^T (64 cols) ----
            float accS[8][4];
            #pragma unroll
            for (int i = 0; i < 8; i++)
                #pragma unroll
                for (int q = 0; q < 4; q++) accS[i][q] = 0.0f;
            #pragma unroll
            for (int ks = 0; ks < 3; ks++) {
                #pragma unroll
                for (int pair = 0; pair < 4; pair++) {
                    uint32_t r4[4];
                    ldm_x4(r4, kb + half * (64 * KSTR * 2) + pair * (16 * KSTR * 2) + ks * 32);
                    mma16816(accS[2 * pair], qf[ks], r4);
                    mma16816(accS[2 * pair + 1], qf[ks], r4 + 2);
                }
            }
            // ---- P = ex2(S) -> A-frags (MUFU) ----
            uint32_t pf[4][4];
            #pragma unroll
            for (int ks2 = 0; ks2 < 4; ks2++) {
                float e0 = fex2(accS[2 * ks2][0]), e1 = fex2(accS[2 * ks2][1]);
                float e2 = fex2(accS[2 * ks2][2]), e3 = fex2(accS[2 * ks2][3]);
                float f0 = fex2(accS[2 * ks2 + 1][0]), f1 = fex2(accS[2 * ks2 + 1][1]);
                float f2 = fex2(accS[2 * ks2 + 1][2]), f3 = fex2(accS[2 * ks2 + 1][3]);
                pf[ks2][0] = packbf2(e0, e1);
                pf[ks2][1] = packbf2(e2, e3);
                pf[ks2][2] = packbf2(f0, f1);
                pf[ks2][3] = packbf2(f2, f3);
            }
            // ---- O += P @ [V | 1] : 6 n-tiles, tile 5 = rowsum ----
            #pragma unroll
            for (int ks2 = 0; ks2 < 4; ks2++) {
                const uint32_t vr = vb + half * (64 * VSTR * 2) + ks2 * (16 * VSTR * 2);
                uint32_t bb[6][2];
                #pragma unroll
                for (int pp = 0; pp < 3; pp++) {
                    uint32_t r4[4];
                    ldm_x4t(r4, vr + pp * 32);
                    bb[2 * pp][0] = r4[0]; bb[2 * pp][1] = r4[1];
                    bb[2 * pp + 1][0] = r4[2]; bb[2 * pp + 1][1] = r4[3];
                }
                #pragma unroll
                for (int nt = 0; nt < 6; nt++)
                    mma16816(accO[nt], pf[ks2], bb[nt]);
            }
        }
    };

    loadKV(0, 0);
    loadKV(1, 1);
    #pragma unroll 1
    for (int kt = 0; kt < 16; kt++) {
        if (kt < 15) cpa_wait<1>();
        else         cpa_wait<0>();
        __syncthreads();
        if (kt + 2 < 16) loadKV(kt + 2, (kt + 2) % 3);
        compute(kt % 3);
    }

    // ---- normalize (rowsum = accO[5]) + write ----
    const float i0 = 1.0f / accO[5][0], i1 = 1.0f / accO[5][2];
    const int r0 = b * LQ + m0 + wid * 16 + g, r1 = r0 + 8;
    #pragma unroll
    for (int nt = 0; nt < 5; nt++) {
        int col = h * HD + nt * 8 + 2 * t;
        *(uint32_t*)(attn + (size_t)r0 * DIM + col) = packbf2(accO[nt][0] * i0, accO[nt][1] * i0);
        *(uint32_t*)(attn + (size_t)r1 * DIM + col) = packbf2(accO[nt][2] * i1, accO[nt][3] * i1);
    }
}

// ---------------- LayerNorm: warp-per-row, no block barriers -----------------
__global__ void __launch_bounds__(256) ln_k(const float* __restrict__ x,
                                            const float* __restrict__ g,
                                            const float* __restrict__ b,
                                            bf16* __restrict__ y) {
    const int wid = threadIdx.x >> 5, lane = threadIdx.x & 31;
    const int row = blockIdx.x * 8 + wid;
    const float* xr = x + (size_t)row * DIM;

    float v[10];
    float s = 0.0f;
    #pragma unroll
    for (int i = 0; i < 10; i++) { v[i] = xr[i * 32 + lane]; s += v[i]; }
    #pragma unroll
    for (int o = 16; o > 0; o >>= 1) s += __shfl_xor_sync(0xffffffffu, s, o);
    const float mean = s * (1.0f / DIM);

    float s2 = 0.0f;
    #pragma unroll
    for (int i = 0; i < 10; i++) { float d = v[i] - mean; s2 += d * d; }
    #pragma unroll
    for (int o = 16; o > 0; o >>= 1) s2 += __shfl_xor_sync(0xffffffffu, s2, o);
    const float inv = rsqrtf(s2 * (1.0f / DIM) + 1e-5f);

    bf16* yr = y + (size_t)row * DIM;
    #pragma unroll
    for (int i = 0; i < 10; i++) {
        int c = i * 32 + lane;
        yr[c] = __float2bfloat16((v[i] - mean) * inv * g[c] + b[c]);
    }
}

// ---------------- Merged prep ----------------
__global__ void prep_k(const float* __restrict__ wq1, const float* __restrict__ wk1,
                       const float* __restrict__ wv1, const float* __restrict__ wo1,
                       const float* __restrict__ wvh, const float* __restrict__ wo2,
                       const float* __restrict__ wff1, const float* __restrict__ wff2,
                       const float* __restrict__ bff1) {
    int idx = blockIdx.x * 256 + threadIdx.x;
    if (idx < 102400) {
        int n = idx % 320, k = idx / 320;
        float s = 0.0f;
        for (int j = 0; j < 320; j++) s += wvh[k * 320 + j] * wo2[j * 320 + n];
        g_w2t[n * 320 + k] = __float2bfloat16(s);
    } else if (idx < 204800) {
        int i = idx - 102400; int n = i / 320, k = i % 320;
        g_wqkvt[i] = __float2bfloat16(wq1[k * 320 + n]);
    } else if (idx < 307200) {
        int i = idx - 204800; int n = i / 320, k = i % 320;
        g_wqkvt[102400 + i] = __float2bfloat16(wk1[k * 320 + n]);
    } else if (idx < 409600) {
        int i = idx - 307200; int n = i / 320, k = i % 320;
        g_wqkvt[204800 + i] = __float2bfloat16(wv1[k * 320 + n]);
    } else if (idx < 512000) {
        int i = idx - 409600; int n = i / 320, k = i % 320;
        g_wo1t[i] = __float2bfloat16(wo1[k * 320 + n]);
    } else if (idx < 921600) {
        int i = idx - 512000; int n = i / 1280, k = i % 1280;
        g_wff2t[i] = __float2bfloat16(wff2[k * 320 + n]);
    } else if (idx < 1740800) {
        int i = idx - 921600; int c = i / 320, k = i % 320;
        int j = (c >> 1) + (c & 1) * FFD;
        g_wff1t[i] = __float2bfloat16(wff1[(size_t)k * 2 * FFD + j]);
    } else if (idx < 1743360) {
        int c = idx - 1740800;
        g_bffi[c] = bff1[(c >> 1) + (c & 1) * FFD];
    }
}

// ---------------- Launch ----------------
extern "C" void kernel_launch(void* const* d_in, const int* in_sizes, int n_in,
                              void* d_out, int out_size) {
    (void)in_sizes; (void)n_in; (void)out_size;
    const float* hidden = (const float*)d_in[0];
    const float* ln1_g = (const float*)d_in[2];
    const float* ln1_b = (const float*)d_in[3];
    const float* wq1   = (const float*)d_in[4];
    const float* wk1   = (const float*)d_in[5];
    const float* wv1   = (const float*)d_in[6];
    const float* wo1   = (const float*)d_in[7];
    const float* bo1   = (const float*)d_in[8];
    const float* ln2_g = (const float*)d_in[9];
    const float* ln2_b = (const float*)d_in[10];
    const float* wvh   = (const float*)d_in[13];
    const float* wo2   = (const float*)d_in[14];
    const float* bo2   = (const float*)d_in[15];
    const float* ln3_g = (const float*)d_in[16];
    const float* ln3_b = (const float*)d_in[17];
    const float* wff1  = (const float*)d_in[18];
    const float* bff1  = (const float*)d_in[19];
    const float* wff2  = (const float*)d_in[20];
    const float* bff2  = (const float*)d_in[21];
    float* out = (float*)d_out;

    bf16 *s_lnb, *s_qkv, *s_attn, *s_ffin;
    bf16 *s_wqkvt, *s_wo1t, *s_w2t, *s_wff1t, *s_wff2t;
    float *s_res, *s_res2, *s_bffi;
    cudaGetSymbolAddress((void**)&s_lnb, g_lnb);
    cudaGetSymbolAddress((void**)&s_qkv, g_qkv);
    cudaGetSymbolAddress((void**)&s_attn, g_attn);
    cudaGetSymbolAddress((void**)&s_res, g_res);
    cudaGetSymbolAddress((void**)&s_res2, g_res2);
    cudaGetSymbolAddress((void**)&s_ffin, g_ffin);
    cudaGetSymbolAddress((void**)&s_wqkvt, g_wqkvt);
    cudaGetSymbolAddress((void**)&s_wo1t, g_wo1t);
    cudaGetSymbolAddress((void**)&s_w2t, g_w2t);
    cudaGetSymbolAddress((void**)&s_wff1t, g_wff1t);
    cudaGetSymbolAddress((void**)&s_wff2t, g_wff2t);
    cudaGetSymbolAddress((void**)&s_bffi, g_bffi);

    cudaFuncSetAttribute(flash_k, cudaFuncAttributeMaxDynamicSharedMemorySize, FL_SMEM);
    cudaFuncSetAttribute(gemm_k<1, 128>, cudaFuncAttributeMaxDynamicSharedMemorySize, GEMM_SMEM_128);
    cudaFuncSetAttribute(gemm_k<3, 128>, cudaFuncAttributeMaxDynamicSharedMemorySize, GEMM_SMEM_128);
    cudaFuncSetAttribute(gemm_k<0, 64>,  cudaFuncAttributeMaxDynamicSharedMemorySize, GEMM_SMEM_64);

    GP p{};

    // 1. weight prep
    prep_k<<<(1743360 + 255) / 256, 256>>>(wq1, wk1, wv1, wo1, wvh, wo2, wff1, wff2, bff1);

    // 2. LN1 + fused QKV GEMM (Q columns pre-scaled by PRESCALE)
    ln_k<<<NROWS / 8, 256>>>(hidden, ln1_g, ln1_b, s_lnb);
    p = GP{ s_lnb, DIM,  s_wqkvt, DIM, QKVN,
            nullptr, s_qkv, QKVN,  nullptr, nullptr, NROWS, QKVN, DIM,
            PRESCALE, DIM };
    gemm_k<1, 128><<<dim3(8, 32), 256, GEMM_SMEM_128>>>(p);

    // 3. fused flash attention
    flash_k<<<dim3(LQ / 128, BH), 256, FL_SMEM>>>(s_qkv, s_attn);

    // 4. wo1 + bias + residual
    p = GP{ s_attn, DIM,  s_wo1t, DIM, DIM,
            s_res, nullptr, DIM,  bo1, hidden, NROWS, DIM, DIM, 1.0f, 0 };
    gemm_k<0, 64><<<dim3(5, 32), 256, GEMM_SMEM_64>>>(p);

    // 5. LN2 + folded cross-attn + residual
    ln_k<<<NROWS / 8, 256>>>(s_res, ln2_g, ln2_b, s_lnb);
    p = GP{ s_lnb, DIM,  s_w2t, DIM, DIM,
            s_res2, nullptr, DIM,  bo2, s_res, NROWS, DIM, DIM, 1.0f, 0 };
    gemm_k<0, 64><<<dim3(5, 32), 256, GEMM_SMEM_64>>>(p);

    // 6. LN3 + FF1 (fused GEGLU) + FF2 + residual
    ln_k<<<NROWS / 8, 256>>>(s_res2, ln3_g, ln3_b, s_lnb);
    p = GP{ s_lnb, DIM,  s_wff1t, DIM, 2 * FFD,
            nullptr, s_ffin, FFD,  s_bffi, nullptr, NROWS, 2 * FFD, DIM, 1.0f, 0 };
    gemm_k<3, 128><<<dim3(20, 32), 256, GEMM_SMEM_128>>>(p);
    p = GP{ s_ffin, FFD,  s_wff2t, FFD, DIM,
            out, nullptr, DIM,  bff2, s_res2, NROWS, DIM, FFD, 1.0f, 0 };
    gemm_k<0, 64><<<dim3(5, 32), 256, GEMM_SMEM_64>>>(p);
}